// round 3
// baseline (speedup 1.0000x reference)
#include <cuda_runtime.h>

#define B_  64
#define S_  197
#define E_  768
#define H_  12
#define HD_ 64
#define M_  (B_ * S_)          // 12608

// Scratch buffers (allocation-free rule: __device__ globals)
__device__ float g_Q[B_ * S_ * E_];
__device__ float g_K[B_ * S_ * E_];
__device__ float g_V[B_ * S_ * E_];
__device__ float g_A[B_ * S_ * E_];

// ---------------------------------------------------------------------------
// SGEMM (NT): C[M,N] = A[M,K] @ W[N,K]^T + bias[N]
// 128x128 tile, BK=8, 256 threads, 8x8 register blocking.
// N and K are exact multiples of the tile (768); only M needs guards.
// ---------------------------------------------------------------------------
#define BM 128
#define BN 128
#define BK 8
#define TM 8
#define TN 8

__global__ __launch_bounds__(256, 1) void sgemm_nt_bias(
    const float* __restrict__ A, const float* __restrict__ Wt,
    const float* __restrict__ bias, float* __restrict__ C,
    int M, int N, int K)
{
    __shared__ float As[BK][BM];
    __shared__ float Bs[BK][BN];

    const int tid = threadIdx.x;
    const int bn = blockIdx.x, bm = blockIdx.y;
    const int loadRow = tid >> 1;          // 0..127
    const int loadCol = (tid & 1) << 2;    // 0 or 4
    const int tr = tid >> 4;               // 0..15
    const int tc = tid & 15;               // 0..15

    const int aRow = bm * BM + loadRow;
    const bool aOk = aRow < M;
    const float* Ap = A  + (size_t)aRow * K + loadCol;
    const float* Wp = Wt + (size_t)(bn * BN + loadRow) * K + loadCol;

    float acc[TM][TN];
#pragma unroll
    for (int i = 0; i < TM; i++)
#pragma unroll
        for (int j = 0; j < TN; j++) acc[i][j] = 0.f;

    for (int k0 = 0; k0 < K; k0 += BK) {
        float4 a4 = aOk ? *(const float4*)Ap : make_float4(0.f, 0.f, 0.f, 0.f);
        float4 b4 = *(const float4*)Wp;
        Ap += BK; Wp += BK;

        As[loadCol + 0][loadRow] = a4.x;
        As[loadCol + 1][loadRow] = a4.y;
        As[loadCol + 2][loadRow] = a4.z;
        As[loadCol + 3][loadRow] = a4.w;
        Bs[loadCol + 0][loadRow] = b4.x;
        Bs[loadCol + 1][loadRow] = b4.y;
        Bs[loadCol + 2][loadRow] = b4.z;
        Bs[loadCol + 3][loadRow] = b4.w;
        __syncthreads();

#pragma unroll
        for (int kk = 0; kk < BK; kk++) {
            float rM[TM], rN[TN];
            *(float4*)&rM[0] = *(const float4*)&As[kk][tr * TM];
            *(float4*)&rM[4] = *(const float4*)&As[kk][tr * TM + 4];
            *(float4*)&rN[0] = *(const float4*)&Bs[kk][tc * TN];
            *(float4*)&rN[4] = *(const float4*)&Bs[kk][tc * TN + 4];
#pragma unroll
            for (int i = 0; i < TM; i++)
#pragma unroll
                for (int j = 0; j < TN; j++)
                    acc[i][j] = fmaf(rM[i], rN[j], acc[i][j]);
        }
        __syncthreads();
    }

    const int cCol = bn * BN + tc * TN;
    float bv[TN];
    *(float4*)&bv[0] = *(const float4*)&bias[cCol];
    *(float4*)&bv[4] = *(const float4*)&bias[cCol + 4];

#pragma unroll
    for (int i = 0; i < TM; i++) {
        const int r = bm * BM + tr * TM + i;
        if (r < M) {
            float4 o0 = make_float4(acc[i][0] + bv[0], acc[i][1] + bv[1],
                                    acc[i][2] + bv[2], acc[i][3] + bv[3]);
            float4 o1 = make_float4(acc[i][4] + bv[4], acc[i][5] + bv[5],
                                    acc[i][6] + bv[6], acc[i][7] + bv[7]);
            *(float4*)&C[(size_t)r * N + cCol]     = o0;
            *(float4*)&C[(size_t)r * N + cCol + 4] = o1;
        }
    }
}

// ---------------------------------------------------------------------------
// Attention: one CTA per (b, h). Faithful-quirk head split: head (b,h) is
// rows [bh*197, bh*197+197) of the flat (B*H*S, 64) view, i.e. base offset
// bh * 197*64 in the contiguous buffer. Softmax FIRST, then /sqrt(768).
// Q/K/V staged in smem; 8 warps x 4 query-rows each per sweep.
// ---------------------------------------------------------------------------
#define KPAD 68    // padded K-row stride (floats) -> conflict-free float4 LDS
#define ATTW 208   // per-row attention buffer stride

#define ATTN_SMEM_FLOATS (S_ * HD_ + S_ * KPAD + S_ * HD_ + 8 * 4 * ATTW)

__global__ __launch_bounds__(256, 1) void attn_kernel(
    const float* __restrict__ Qg, const float* __restrict__ Kg,
    const float* __restrict__ Vg, float* __restrict__ Og)
{
    extern __shared__ float sm[];
    float* Qs = sm;                      // S_*HD_
    float* Ks = Qs + S_ * HD_;           // S_*KPAD
    float* Vs = Ks + S_ * KPAD;          // S_*HD_
    float* Aw = Vs + S_ * HD_;           // 8 warps * 4 rows * ATTW

    const int tid = threadIdx.x;
    const size_t base = (size_t)blockIdx.x * (S_ * HD_);

    // Stage Q, K (padded), V into smem
    const float4* Q4 = (const float4*)(Qg + base);
    const float4* K4 = (const float4*)(Kg + base);
    const float4* V4 = (const float4*)(Vg + base);
    for (int i = tid; i < S_ * (HD_ / 4); i += 256) {
        ((float4*)Qs)[i] = Q4[i];
        ((float4*)Vs)[i] = V4[i];
        const int row = i >> 4, c = i & 15;
        ((float4*)Ks)[row * (KPAD / 4) + c] = K4[i];
    }
    __syncthreads();

    const int w = tid >> 5, lane = tid & 31;
    float* attw = Aw + w * (4 * ATTW);
    const float4* Qs4 = (const float4*)Qs;
    const float4* Ks4 = (const float4*)Ks;

    int kk[7];
#pragma unroll
    for (int j = 0; j < 7; j++) {
        int k = lane + 32 * j;
        kk[j] = k < S_ ? k : (S_ - 1);
    }

    for (int base_r = 0; base_r < S_; base_r += 32) {
        const int r0 = base_r + w * 4;
        if (r0 >= S_) break;     // uniform per warp

        int rr[4];
#pragma unroll
        for (int ri = 0; ri < 4; ri++) {
            int r = r0 + ri;
            rr[ri] = r < S_ ? r : (S_ - 1);
        }

        // ---- energy: 4 query rows x 7 key slots per lane ----
        float acc[4][7];
#pragma unroll
        for (int ri = 0; ri < 4; ri++)
#pragma unroll
            for (int j = 0; j < 7; j++) acc[ri][j] = 0.f;

#pragma unroll
        for (int d4 = 0; d4 < HD_ / 4; d4++) {
            const float4 q0 = Qs4[rr[0] * 16 + d4];
            const float4 q1 = Qs4[rr[1] * 16 + d4];
            const float4 q2 = Qs4[rr[2] * 16 + d4];
            const float4 q3 = Qs4[rr[3] * 16 + d4];
#pragma unroll
            for (int j = 0; j < 7; j++) {
                const float4 kv = Ks4[kk[j] * (KPAD / 4) + d4];
                acc[0][j] += q0.x * kv.x + q0.y * kv.y + q0.z * kv.z + q0.w * kv.w;
                acc[1][j] += q1.x * kv.x + q1.y * kv.y + q1.z * kv.z + q1.w * kv.w;
                acc[2][j] += q2.x * kv.x + q2.y * kv.y + q2.z * kv.z + q2.w * kv.w;
                acc[3][j] += q3.x * kv.x + q3.y * kv.y + q3.z * kv.z + q3.w * kv.w;
            }
        }

        // ---- softmax (then / sqrt(E), faithful quirk order) ----
#pragma unroll
        for (int ri = 0; ri < 4; ri++) {
            if (r0 + ri >= S_) break;
            float mx = -1e30f;
#pragma unroll
            for (int j = 0; j < 7; j++)
                if (lane + 32 * j < S_) mx = fmaxf(mx, acc[ri][j]);
#pragma unroll
            for (int o = 16; o > 0; o >>= 1)
                mx = fmaxf(mx, __shfl_xor_sync(0xffffffffu, mx, o));
            float sum = 0.f;
#pragma unroll
            for (int j = 0; j < 7; j++) {
                const float e = (lane + 32 * j < S_) ? __expf(acc[ri][j] - mx) : 0.f;
                acc[ri][j] = e;
                sum += e;
            }
#pragma unroll
            for (int o = 16; o > 0; o >>= 1)
                sum += __shfl_xor_sync(0xffffffffu, sum, o);
            const float sc = 0.03608439182435161f / sum;   // (1/sqrt(768)) / sum
#pragma unroll
            for (int j = 0; j < 7; j++) {
                const int k = lane + 32 * j;
                if (k < S_) attw[ri * ATTW + k] = acc[ri][j] * sc;
            }
        }
        __syncwarp();

        // ---- out = att @ V : each lane owns dims (2*lane, 2*lane+1) ----
        const int d0 = lane * 2;
        float o00 = 0.f, o01 = 0.f, o10 = 0.f, o11 = 0.f;
        float o20 = 0.f, o21 = 0.f, o30 = 0.f, o31 = 0.f;
#pragma unroll 4
        for (int k = 0; k < S_; k++) {
            const float2 v = *(const float2*)(Vs + k * HD_ + d0);
            const float a0 = attw[0 * ATTW + k];
            const float a1 = attw[1 * ATTW + k];
            const float a2 = attw[2 * ATTW + k];
            const float a3 = attw[3 * ATTW + k];
            o00 += a0 * v.x; o01 += a0 * v.y;
            o10 += a1 * v.x; o11 += a1 * v.y;
            o20 += a2 * v.x; o21 += a2 * v.y;
            o30 += a3 * v.x; o31 += a3 * v.y;
        }
        if (r0 + 0 < S_) { float2 s = make_float2(o00, o01); *(float2*)(Og + base + (size_t)(r0 + 0) * HD_ + d0) = s; }
        if (r0 + 1 < S_) { float2 s = make_float2(o10, o11); *(float2*)(Og + base + (size_t)(r0 + 1) * HD_ + d0) = s; }
        if (r0 + 2 < S_) { float2 s = make_float2(o20, o21); *(float2*)(Og + base + (size_t)(r0 + 2) * HD_ + d0) = s; }
        if (r0 + 3 < S_) { float2 s = make_float2(o30, o31); *(float2*)(Og + base + (size_t)(r0 + 3) * HD_ + d0) = s; }
        __syncwarp();   // attw reused next sweep
    }
}

// ---------------------------------------------------------------------------
extern "C" void kernel_launch(void* const* d_in, const int* in_sizes, int n_in,
                              void* d_out, int out_size)
{
    const float* x  = (const float*)d_in[0];
    const float* Wq = (const float*)d_in[1];
    const float* bq = (const float*)d_in[2];
    const float* Wk = (const float*)d_in[3];
    const float* bk = (const float*)d_in[4];
    const float* Wv = (const float*)d_in[5];
    const float* bv = (const float*)d_in[6];
    const float* Wo = (const float*)d_in[7];
    const float* bo = (const float*)d_in[8];

    float *Q, *K, *V, *Aa;
    cudaGetSymbolAddress((void**)&Q,  g_Q);
    cudaGetSymbolAddress((void**)&K,  g_K);
    cudaGetSymbolAddress((void**)&V,  g_V);
    cudaGetSymbolAddress((void**)&Aa, g_A);

    dim3 grid(E_ / BN, (M_ + BM - 1) / BM);   // (6, 99)

    sgemm_nt_bias<<<grid, 256>>>(x, Wq, bq, Q, M_, E_, E_);
    sgemm_nt_bias<<<grid, 256>>>(x, Wk, bk, K, M_, E_, E_);
    sgemm_nt_bias<<<grid, 256>>>(x, Wv, bv, V, M_, E_, E_);

    const int smem_bytes = ATTN_SMEM_FLOATS * (int)sizeof(float);   // ~181 KB
    cudaFuncSetAttribute(attn_kernel,
                         cudaFuncAttributeMaxDynamicSharedMemorySize, smem_bytes);
    attn_kernel<<<B_ * H_, 256, smem_bytes>>>(Q, K, V, Aa);

    sgemm_nt_bias<<<grid, 256>>>(Aa, Wo, bo, (float*)d_out, M_, E_, E_);
}

// round 4
// speedup vs baseline: 2.2694x; 2.2694x over previous
#include <cuda_runtime.h>
#include <cstdint>

#define B_  64
#define S_  197
#define E_  768
#define H_  12
#define HD_ 64
#define M_  (B_ * S_)          // 12608

// Scratch buffers (allocation-free rule: __device__ globals)
__device__ float g_Q[B_ * S_ * E_];
__device__ float g_K[B_ * S_ * E_];
__device__ float g_V[B_ * S_ * E_];
__device__ float g_A[B_ * S_ * E_];   // attention output (tf32-rounded)
__device__ float g_X[B_ * S_ * E_];   // tf32-rounded x
__device__ float g_Wq[E_ * E_];
__device__ float g_Wk[E_ * E_];
__device__ float g_Wv[E_ * E_];
__device__ float g_Wp[E_ * E_];

// ---------------------------------------------------------------------------
// helpers
// ---------------------------------------------------------------------------
__device__ __forceinline__ float tf32r(float x) {
    uint32_t u;
    asm("cvt.rna.tf32.f32 %0, %1;" : "=r"(u) : "f"(x));
    return __uint_as_float(u);
}

__global__ void tf32_round_kernel(const float4* __restrict__ in,
                                  float4* __restrict__ out, int n4)
{
    int i = blockIdx.x * blockDim.x + threadIdx.x;
    if (i < n4) {
        float4 v = in[i];
        v.x = tf32r(v.x); v.y = tf32r(v.y); v.z = tf32r(v.z); v.w = tf32r(v.w);
        out[i] = v;
    }
}

__device__ __forceinline__ void cpasync16(void* smem, const void* gmem) {
    uint32_t s = (uint32_t)__cvta_generic_to_shared(smem);
    asm volatile("cp.async.cg.shared.global [%0], [%1], 16;\n" :: "r"(s), "l"(gmem));
}

__device__ __forceinline__ void mma_tf32(float* c, const uint32_t* a, const uint32_t* b) {
    asm volatile(
        "mma.sync.aligned.m16n8k8.row.col.f32.tf32.tf32.f32 "
        "{%0,%1,%2,%3}, {%4,%5,%6,%7}, {%8,%9}, {%0,%1,%2,%3};\n"
        : "+f"(c[0]), "+f"(c[1]), "+f"(c[2]), "+f"(c[3])
        : "r"(a[0]), "r"(a[1]), "r"(a[2]), "r"(a[3]), "r"(b[0]), "r"(b[1]));
}

// ---------------------------------------------------------------------------
// TF32 tensor-core GEMM (NT): C[M,768] = A[M,768] @ W[768,768]^T + bias
// CTA tile 128x128, BK=32, 256 threads (8 warps, 4x2 layout, 32x64 per warp),
// double-buffered smem + cp.async. A/W must be tf32-rounded fp32 bits.
// ---------------------------------------------------------------------------
#define GBK 32
#define SPAD 36    // padded smem row stride (floats)

__global__ __launch_bounds__(256, 1) void mma_nt_bias(
    const float* __restrict__ A, const float* __restrict__ Wt,
    const float* __restrict__ bias, float* __restrict__ C, int M)
{
    constexpr int K = 768, N = 768;
    __shared__ float As[2][128][SPAD];
    __shared__ float Bs[2][128][SPAD];

    const int tid  = threadIdx.x;
    const int bm   = blockIdx.y, bn = blockIdx.x;
    const int wid  = tid >> 5, lane = tid & 31;
    const int gid  = lane >> 2, tig = lane & 3;
    const int r0   = (wid & 3) * 32;      // warp row offset within tile
    const int n0   = (wid >> 2) * 64;     // warp col offset within tile

    float c[2][8][4] = {};

    // per-thread load coords: j = tid + 256*i (i<4): row = j>>3, col4 = j&7
    int lrow[4], lc4[4];
    const float* aSrc[4];
    const float* bSrc[4];
#pragma unroll
    for (int i = 0; i < 4; i++) {
        int j = tid + 256 * i;
        lrow[i] = j >> 3;
        lc4[i]  = (j & 7) * 4;
        int ar = bm * 128 + lrow[i]; if (ar >= M) ar = M - 1;
        aSrc[i] = A  + (size_t)ar * K + lc4[i];
        bSrc[i] = Wt + (size_t)(bn * 128 + lrow[i]) * K + lc4[i];
    }

    // prefetch stage 0
#pragma unroll
    for (int i = 0; i < 4; i++) {
        cpasync16(&As[0][lrow[i]][lc4[i]], aSrc[i]);
        cpasync16(&Bs[0][lrow[i]][lc4[i]], bSrc[i]);
    }
    asm volatile("cp.async.commit_group;\n");

    int buf = 0;
    for (int it = 0; it < K / GBK; it++) {
        if (it + 1 < K / GBK) {
            const int kn = (it + 1) * GBK;
#pragma unroll
            for (int i = 0; i < 4; i++) {
                cpasync16(&As[buf ^ 1][lrow[i]][lc4[i]], aSrc[i] + kn);
                cpasync16(&Bs[buf ^ 1][lrow[i]][lc4[i]], bSrc[i] + kn);
            }
            asm volatile("cp.async.commit_group;\n");
            asm volatile("cp.async.wait_group 1;\n");
        } else {
            asm volatile("cp.async.wait_group 0;\n");
        }
        __syncthreads();

#pragma unroll
        for (int kk = 0; kk < 4; kk++) {
            const int kb = kk * 8;
            uint32_t a[2][4], b[8][2];
#pragma unroll
            for (int t = 0; t < 2; t++) {
                const float* p = &As[buf][r0 + t * 16 + gid][kb + tig];
                a[t][0] = __float_as_uint(p[0]);
                a[t][1] = __float_as_uint(p[8 * SPAD]);
                a[t][2] = __float_as_uint(p[4]);
                a[t][3] = __float_as_uint(p[8 * SPAD + 4]);
            }
#pragma unroll
            for (int u = 0; u < 8; u++) {
                const float* p = &Bs[buf][n0 + u * 8 + gid][kb + tig];
                b[u][0] = __float_as_uint(p[0]);
                b[u][1] = __float_as_uint(p[4]);
            }
#pragma unroll
            for (int t = 0; t < 2; t++)
#pragma unroll
                for (int u = 0; u < 8; u++)
                    mma_tf32(c[t][u], a[t], b[u]);
        }
        __syncthreads();
        buf ^= 1;
    }

    // epilogue: bias + guarded stores
#pragma unroll
    for (int t = 0; t < 2; t++) {
        const int row0 = bm * 128 + r0 + t * 16 + gid;
#pragma unroll
        for (int u = 0; u < 8; u++) {
            const int col = bn * 128 + n0 + u * 8 + 2 * tig;
            const float bx = bias[col], by = bias[col + 1];
            if (row0 < M)
                *(float2*)&C[(size_t)row0 * N + col] =
                    make_float2(c[t][u][0] + bx, c[t][u][1] + by);
            if (row0 + 8 < M)
                *(float2*)&C[(size_t)(row0 + 8) * N + col] =
                    make_float2(c[t][u][2] + bx, c[t][u][3] + by);
        }
    }
}

// ---------------------------------------------------------------------------
// Attention: one CTA per (b, h), 512 threads (16 warps x 4 query rows/sweep).
// Faithful-quirk head split (raw view, no transpose); softmax FIRST then /sqrt(E).
// Output rounded to tf32 so the proj GEMM consumes it directly.
// ---------------------------------------------------------------------------
#define KPAD 68
#define ATTW 200
#define NWARP 16
#define ATTN_SMEM_FLOATS (S_ * HD_ + S_ * KPAD + S_ * HD_ + NWARP * 4 * ATTW)

__global__ __launch_bounds__(512, 1) void attn_kernel(
    const float* __restrict__ Qg, const float* __restrict__ Kg,
    const float* __restrict__ Vg, float* __restrict__ Og)
{
    extern __shared__ float sm[];
    float* Qs = sm;                      // S_*HD_
    float* Ks = Qs + S_ * HD_;           // S_*KPAD
    float* Vs = Ks + S_ * KPAD;          // S_*HD_
    float* Aw = Vs + S_ * HD_;           // NWARP warps * 4 rows * ATTW

    const int tid = threadIdx.x;
    const size_t base = (size_t)blockIdx.x * (S_ * HD_);

    const float4* Q4 = (const float4*)(Qg + base);
    const float4* K4 = (const float4*)(Kg + base);
    const float4* V4 = (const float4*)(Vg + base);
    for (int i = tid; i < S_ * (HD_ / 4); i += 512) {
        ((float4*)Qs)[i] = Q4[i];
        ((float4*)Vs)[i] = V4[i];
        const int row = i >> 4, c = i & 15;
        ((float4*)Ks)[row * (KPAD / 4) + c] = K4[i];
    }
    __syncthreads();

    const int w = tid >> 5, lane = tid & 31;
    float* attw = Aw + w * (4 * ATTW);
    const float4* Qs4 = (const float4*)Qs;
    const float4* Ks4 = (const float4*)Ks;

    int kk[7];
#pragma unroll
    for (int j = 0; j < 7; j++) {
        int k = lane + 32 * j;
        kk[j] = k < S_ ? k : (S_ - 1);
    }

    for (int base_r = 0; base_r < S_; base_r += 4 * NWARP) {
        const int r0 = base_r + w * 4;
        if (r0 >= S_) break;     // uniform per warp

        int rr[4];
#pragma unroll
        for (int ri = 0; ri < 4; ri++) {
            int r = r0 + ri;
            rr[ri] = r < S_ ? r : (S_ - 1);
        }

        // ---- energy ----
        float acc[4][7];
#pragma unroll
        for (int ri = 0; ri < 4; ri++)
#pragma unroll
            for (int j = 0; j < 7; j++) acc[ri][j] = 0.f;

#pragma unroll
        for (int d4 = 0; d4 < HD_ / 4; d4++) {
            const float4 q0 = Qs4[rr[0] * 16 + d4];
            const float4 q1 = Qs4[rr[1] * 16 + d4];
            const float4 q2 = Qs4[rr[2] * 16 + d4];
            const float4 q3 = Qs4[rr[3] * 16 + d4];
#pragma unroll
            for (int j = 0; j < 7; j++) {
                const float4 kv = Ks4[kk[j] * (KPAD / 4) + d4];
                acc[0][j] += q0.x * kv.x + q0.y * kv.y + q0.z * kv.z + q0.w * kv.w;
                acc[1][j] += q1.x * kv.x + q1.y * kv.y + q1.z * kv.z + q1.w * kv.w;
                acc[2][j] += q2.x * kv.x + q2.y * kv.y + q2.z * kv.z + q2.w * kv.w;
                acc[3][j] += q3.x * kv.x + q3.y * kv.y + q3.z * kv.z + q3.w * kv.w;
            }
        }

        // ---- softmax (then / sqrt(E)) ----
#pragma unroll
        for (int ri = 0; ri < 4; ri++) {
            if (r0 + ri >= S_) break;
            float mx = -1e30f;
#pragma unroll
            for (int j = 0; j < 7; j++)
                if (lane + 32 * j < S_) mx = fmaxf(mx, acc[ri][j]);
#pragma unroll
            for (int o = 16; o > 0; o >>= 1)
                mx = fmaxf(mx, __shfl_xor_sync(0xffffffffu, mx, o));
            float sum = 0.f;
#pragma unroll
            for (int j = 0; j < 7; j++) {
                const float e = (lane + 32 * j < S_) ? __expf(acc[ri][j] - mx) : 0.f;
                acc[ri][j] = e;
                sum += e;
            }
#pragma unroll
            for (int o = 16; o > 0; o >>= 1)
                sum += __shfl_xor_sync(0xffffffffu, sum, o);
            const float sc = 0.03608439182435161f / sum;   // (1/sqrt(768)) / sum
#pragma unroll
            for (int j = 0; j < 7; j++) {
                const int k = lane + 32 * j;
                if (k < S_) attw[ri * ATTW + k] = acc[ri][j] * sc;
            }
        }
        __syncwarp();

        // ---- out = att @ V : lane owns dims (2*lane, 2*lane+1) ----
        const int d0 = lane * 2;
        float o00 = 0.f, o01 = 0.f, o10 = 0.f, o11 = 0.f;
        float o20 = 0.f, o21 = 0.f, o30 = 0.f, o31 = 0.f;
#pragma unroll 4
        for (int k = 0; k < S_; k++) {
            const float2 v = *(const float2*)(Vs + k * HD_ + d0);
            const float a0 = attw[0 * ATTW + k];
            const float a1 = attw[1 * ATTW + k];
            const float a2 = attw[2 * ATTW + k];
            const float a3 = attw[3 * ATTW + k];
            o00 += a0 * v.x; o01 += a0 * v.y;
            o10 += a1 * v.x; o11 += a1 * v.y;
            o20 += a2 * v.x; o21 += a2 * v.y;
            o30 += a3 * v.x; o31 += a3 * v.y;
        }
        if (r0 + 0 < S_) *(float2*)(Og + base + (size_t)(r0 + 0) * HD_ + d0) = make_float2(tf32r(o00), tf32r(o01));
        if (r0 + 1 < S_) *(float2*)(Og + base + (size_t)(r0 + 1) * HD_ + d0) = make_float2(tf32r(o10), tf32r(o11));
        if (r0 + 2 < S_) *(float2*)(Og + base + (size_t)(r0 + 2) * HD_ + d0) = make_float2(tf32r(o20), tf32r(o21));
        if (r0 + 3 < S_) *(float2*)(Og + base + (size_t)(r0 + 3) * HD_ + d0) = make_float2(tf32r(o30), tf32r(o31));
        __syncwarp();   // attw reused next sweep
    }
}

// ---------------------------------------------------------------------------
extern "C" void kernel_launch(void* const* d_in, const int* in_sizes, int n_in,
                              void* d_out, int out_size)
{
    const float* x  = (const float*)d_in[0];
    const float* Wq = (const float*)d_in[1];
    const float* bq = (const float*)d_in[2];
    const float* Wk = (const float*)d_in[3];
    const float* bk = (const float*)d_in[4];
    const float* Wv = (const float*)d_in[5];
    const float* bv = (const float*)d_in[6];
    const float* Wo = (const float*)d_in[7];
    const float* bo = (const float*)d_in[8];

    float *Q, *K, *V, *Aa, *Xt, *Wqt, *Wkt, *Wvt, *Wpt;
    cudaGetSymbolAddress((void**)&Q,   g_Q);
    cudaGetSymbolAddress((void**)&K,   g_K);
    cudaGetSymbolAddress((void**)&V,   g_V);
    cudaGetSymbolAddress((void**)&Aa,  g_A);
    cudaGetSymbolAddress((void**)&Xt,  g_X);
    cudaGetSymbolAddress((void**)&Wqt, g_Wq);
    cudaGetSymbolAddress((void**)&Wkt, g_Wk);
    cudaGetSymbolAddress((void**)&Wvt, g_Wv);
    cudaGetSymbolAddress((void**)&Wpt, g_Wp);

    // 1) tf32-round x and the four weight matrices
    const int nx4 = (M_ * E_) / 4;     // 2,420,736
    const int nw4 = (E_ * E_) / 4;     //   147,456
    tf32_round_kernel<<<(nx4 + 255) / 256, 256>>>((const float4*)x,  (float4*)Xt,  nx4);
    tf32_round_kernel<<<(nw4 + 255) / 256, 256>>>((const float4*)Wq, (float4*)Wqt, nw4);
    tf32_round_kernel<<<(nw4 + 255) / 256, 256>>>((const float4*)Wk, (float4*)Wkt, nw4);
    tf32_round_kernel<<<(nw4 + 255) / 256, 256>>>((const float4*)Wv, (float4*)Wvt, nw4);
    tf32_round_kernel<<<(nw4 + 255) / 256, 256>>>((const float4*)Wo, (float4*)Wpt, nw4);

    // 2) Q/K/V projections on tensor cores
    dim3 grid(E_ / 128, (M_ + 127) / 128);   // (6, 99)
    mma_nt_bias<<<grid, 256>>>(Xt, Wqt, bq, Q, M_);
    mma_nt_bias<<<grid, 256>>>(Xt, Wkt, bk, K, M_);
    mma_nt_bias<<<grid, 256>>>(Xt, Wvt, bv, V, M_);

    // 3) attention
    const int smem_bytes = ATTN_SMEM_FLOATS * (int)sizeof(float);   // ~205.6 KB
    cudaFuncSetAttribute(attn_kernel,
                         cudaFuncAttributeMaxDynamicSharedMemorySize, smem_bytes);
    attn_kernel<<<B_ * H_, 512, smem_bytes>>>(Q, K, V, Aa);

    // 4) output projection
    mma_nt_bias<<<grid, 256>>>(Aa, Wpt, bo, (float*)d_out, M_);
}

// round 7
// speedup vs baseline: 2.4523x; 1.0806x over previous
#include <cuda_runtime.h>
#include <cstdint>

#define B_  64
#define S_  197
#define E_  768
#define H_  12
#define HD_ 64
#define M_  (B_ * S_)          // 12608

// Scratch buffers (allocation-free rule: __device__ globals)
__device__ float g_Q[B_ * S_ * E_];
__device__ float g_K[B_ * S_ * E_];
__device__ float g_V[B_ * S_ * E_];
__device__ float g_A[B_ * S_ * E_];   // attention output (tf32-rounded)
__device__ float g_X[B_ * S_ * E_];   // tf32-rounded x
__device__ float g_Wq[E_ * E_];
__device__ float g_Wk[E_ * E_];
__device__ float g_Wv[E_ * E_];
__device__ float g_Wp[E_ * E_];

// ---------------------------------------------------------------------------
// helpers
// ---------------------------------------------------------------------------
__device__ __forceinline__ float tf32r(float x) {
    uint32_t u;
    asm("cvt.rna.tf32.f32 %0, %1;" : "=r"(u) : "f"(x));
    return __uint_as_float(u);
}

__global__ void tf32_round_kernel(const float4* __restrict__ in,
                                  float4* __restrict__ out, int n4)
{
    int i = blockIdx.x * blockDim.x + threadIdx.x;
    if (i < n4) {
        float4 v = in[i];
        v.x = tf32r(v.x); v.y = tf32r(v.y); v.z = tf32r(v.z); v.w = tf32r(v.w);
        out[i] = v;
    }
}

__device__ __forceinline__ void cpasync16(void* smem, const void* gmem) {
    uint32_t s = (uint32_t)__cvta_generic_to_shared(smem);
    asm volatile("cp.async.cg.shared.global [%0], [%1], 16;\n" :: "r"(s), "l"(gmem));
}

__device__ __forceinline__ void mma_tf32(float* c, const uint32_t* a, const uint32_t* b) {
    asm volatile(
        "mma.sync.aligned.m16n8k8.row.col.f32.tf32.tf32.f32 "
        "{%0,%1,%2,%3}, {%4,%5,%6,%7}, {%8,%9}, {%0,%1,%2,%3};\n"
        : "+f"(c[0]), "+f"(c[1]), "+f"(c[2]), "+f"(c[3])
        : "r"(a[0]), "r"(a[1]), "r"(a[2]), "r"(a[3]), "r"(b[0]), "r"(b[1]));
}

// ---------------------------------------------------------------------------
// TF32 tensor-core GEMM (NT): C[M,768] = A[M,768] @ W[768,768]^T + bias
// CTA tile 128x128, BK=32, 256 threads (8 warps, 4x2 layout, 32x64 per warp),
// double-buffered DYNAMIC smem + cp.async, 2 CTAs/SM.
// blockIdx.z selects (W, bias, C) -> fused QKV in one launch.
// ---------------------------------------------------------------------------
#define GBK 32
#define SPAD 36    // padded smem row stride (floats)
#define GEMM_SMEM_BYTES (2 * 2 * 128 * SPAD * 4)   // As+Bs, double buffered: 73728

__global__ __launch_bounds__(256, 2) void mma_nt_bias(
    const float* __restrict__ A,
    const float* __restrict__ W0, const float* __restrict__ W1,
    const float* __restrict__ W2,
    const float* __restrict__ b0, const float* __restrict__ b1,
    const float* __restrict__ b2,
    float* __restrict__ C0, float* __restrict__ C1, float* __restrict__ C2,
    int M)
{
    constexpr int K = 768, N = 768;
    extern __shared__ float smg[];
    float* As = smg;                       // [2][128][SPAD]
    float* Bs = smg + 2 * 128 * SPAD;      // [2][128][SPAD]

    const int tid = threadIdx.x;
    const int bm  = blockIdx.y, bn = blockIdx.x, z = blockIdx.z;
    const int wid = tid >> 5, lane = tid & 31;
    const int gid = lane >> 2, tig = lane & 3;
    const int r0  = (wid & 3) * 32;      // warp row offset within tile
    const int n0  = (wid >> 2) * 64;     // warp col offset within tile

    const float* Wt   = (z == 0) ? W0 : (z == 1) ? W1 : W2;
    const float* bias = (z == 0) ? b0 : (z == 1) ? b1 : b2;
    float*       C    = (z == 0) ? C0 : (z == 1) ? C1 : C2;

    float c[2][8][4] = {};

    // per-thread load coords: j = tid + 256*i (i<4): row = j>>3, col4 = j&7
    int lrow[4], lc4[4];
    const float* aSrc[4];
    const float* bSrc[4];
#pragma unroll
    for (int i = 0; i < 4; i++) {
        int j = tid + 256 * i;
        lrow[i] = j >> 3;
        lc4[i]  = (j & 7) * 4;
        int ar = bm * 128 + lrow[i]; if (ar >= M) ar = M - 1;
        aSrc[i] = A  + (size_t)ar * K + lc4[i];
        bSrc[i] = Wt + (size_t)(bn * 128 + lrow[i]) * K + lc4[i];
    }

    // prefetch stage 0
#pragma unroll
    for (int i = 0; i < 4; i++) {
        cpasync16(&As[(size_t)lrow[i] * SPAD + lc4[i]], aSrc[i]);
        cpasync16(&Bs[(size_t)lrow[i] * SPAD + lc4[i]], bSrc[i]);
    }
    asm volatile("cp.async.commit_group;\n");

    int buf = 0;
    for (int it = 0; it < K / GBK; it++) {
        if (it + 1 < K / GBK) {
            const int kn = (it + 1) * GBK;
            float* An = As + (size_t)(buf ^ 1) * 128 * SPAD;
            float* Bn = Bs + (size_t)(buf ^ 1) * 128 * SPAD;
#pragma unroll
            for (int i = 0; i < 4; i++) {
                cpasync16(&An[(size_t)lrow[i] * SPAD + lc4[i]], aSrc[i] + kn);
                cpasync16(&Bn[(size_t)lrow[i] * SPAD + lc4[i]], bSrc[i] + kn);
            }
            asm volatile("cp.async.commit_group;\n");
            asm volatile("cp.async.wait_group 1;\n");
        } else {
            asm volatile("cp.async.wait_group 0;\n");
        }
        __syncthreads();

        const float* Ac = As + (size_t)buf * 128 * SPAD;
        const float* Bc = Bs + (size_t)buf * 128 * SPAD;
#pragma unroll
        for (int kk = 0; kk < 4; kk++) {
            const int kb = kk * 8;
            uint32_t a[2][4], b[8][2];
#pragma unroll
            for (int t = 0; t < 2; t++) {
                const float* p = &Ac[(size_t)(r0 + t * 16 + gid) * SPAD + kb + tig];
                a[t][0] = __float_as_uint(p[0]);
                a[t][1] = __float_as_uint(p[8 * SPAD]);
                a[t][2] = __float_as_uint(p[4]);
                a[t][3] = __float_as_uint(p[8 * SPAD + 4]);
            }
#pragma unroll
            for (int u = 0; u < 8; u++) {
                const float* p = &Bc[(size_t)(n0 + u * 8 + gid) * SPAD + kb + tig];
                b[u][0] = __float_as_uint(p[0]);
                b[u][1] = __float_as_uint(p[4]);
            }
#pragma unroll
            for (int t = 0; t < 2; t++)
#pragma unroll
                for (int u = 0; u < 8; u++)
                    mma_tf32(c[t][u], a[t], b[u]);
        }
        __syncthreads();
        buf ^= 1;
    }

    // epilogue: bias + guarded stores
#pragma unroll
    for (int t = 0; t < 2; t++) {
        const int row0 = bm * 128 + r0 + t * 16 + gid;
#pragma unroll
        for (int u = 0; u < 8; u++) {
            const int col = bn * 128 + n0 + u * 8 + 2 * tig;
            const float bx = bias[col], by = bias[col + 1];
            if (row0 < M)
                *(float2*)&C[(size_t)row0 * N + col] =
                    make_float2(c[t][u][0] + bx, c[t][u][1] + by);
            if (row0 + 8 < M)
                *(float2*)&C[(size_t)(row0 + 8) * N + col] =
                    make_float2(c[t][u][2] + bx, c[t][u][3] + by);
        }
    }
}

// ---------------------------------------------------------------------------
// Attention: one CTA per (b, h), 512 threads (16 warps x 4 query rows/sweep).
// Faithful-quirk head split (raw view, no transpose); softmax FIRST then /sqrt(E).
// Output rounded to tf32 so the proj GEMM consumes it directly.
// ---------------------------------------------------------------------------
#define KPAD 68
#define ATTW 200
#define NWARP 16
#define ATTN_SMEM_FLOATS (S_ * HD_ + S_ * KPAD + S_ * HD_ + NWARP * 4 * ATTW)

__global__ __launch_bounds__(512, 1) void attn_kernel(
    const float* __restrict__ Qg, const float* __restrict__ Kg,
    const float* __restrict__ Vg, float* __restrict__ Og)
{
    extern __shared__ float sm[];
    float* Qs = sm;
    float* Ks = Qs + S_ * HD_;
    float* Vs = Ks + S_ * KPAD;
    float* Aw = Vs + S_ * HD_;

    const int tid = threadIdx.x;
    const size_t base = (size_t)blockIdx.x * (S_ * HD_);

    const float4* Q4 = (const float4*)(Qg + base);
    const float4* K4 = (const float4*)(Kg + base);
    const float4* V4 = (const float4*)(Vg + base);
    for (int i = tid; i < S_ * (HD_ / 4); i += 512) {
        ((float4*)Qs)[i] = Q4[i];
        ((float4*)Vs)[i] = V4[i];
        const int row = i >> 4, c = i & 15;
        ((float4*)Ks)[row * (KPAD / 4) + c] = K4[i];
    }
    __syncthreads();

    const int w = tid >> 5, lane = tid & 31;
    float* attw = Aw + w * (4 * ATTW);
    const float4* Qs4 = (const float4*)Qs;
    const float4* Ks4 = (const float4*)Ks;

    int kk[7];
#pragma unroll
    for (int j = 0; j < 7; j++) {
        int k = lane + 32 * j;
        kk[j] = k < S_ ? k : (S_ - 1);
    }

    for (int base_r = 0; base_r < S_; base_r += 4 * NWARP) {
        const int r0 = base_r + w * 4;
        if (r0 >= S_) break;

        int rr[4];
#pragma unroll
        for (int ri = 0; ri < 4; ri++) {
            int r = r0 + ri;
            rr[ri] = r < S_ ? r : (S_ - 1);
        }

        float acc[4][7];
#pragma unroll
        for (int ri = 0; ri < 4; ri++)
#pragma unroll
            for (int j = 0; j < 7; j++) acc[ri][j] = 0.f;

#pragma unroll
        for (int d4 = 0; d4 < HD_ / 4; d4++) {
            const float4 q0 = Qs4[rr[0] * 16 + d4];
            const float4 q1 = Qs4[rr[1] * 16 + d4];
            const float4 q2 = Qs4[rr[2] * 16 + d4];
            const float4 q3 = Qs4[rr[3] * 16 + d4];
#pragma unroll
            for (int j = 0; j < 7; j++) {
                const float4 kv = Ks4[kk[j] * (KPAD / 4) + d4];
                acc[0][j] += q0.x * kv.x + q0.y * kv.y + q0.z * kv.z + q0.w * kv.w;
                acc[1][j] += q1.x * kv.x + q1.y * kv.y + q1.z * kv.z + q1.w * kv.w;
                acc[2][j] += q2.x * kv.x + q2.y * kv.y + q2.z * kv.z + q2.w * kv.w;
                acc[3][j] += q3.x * kv.x + q3.y * kv.y + q3.z * kv.z + q3.w * kv.w;
            }
        }

#pragma unroll
        for (int ri = 0; ri < 4; ri++) {
            if (r0 + ri >= S_) break;
            float mx = -1e30f;
#pragma unroll
            for (int j = 0; j < 7; j++)
                if (lane + 32 * j < S_) mx = fmaxf(mx, acc[ri][j]);
#pragma unroll
            for (int o = 16; o > 0; o >>= 1)
                mx = fmaxf(mx, __shfl_xor_sync(0xffffffffu, mx, o));
            float sum = 0.f;
#pragma unroll
            for (int j = 0; j < 7; j++) {
                const float e = (lane + 32 * j < S_) ? __expf(acc[ri][j] - mx) : 0.f;
                acc[ri][j] = e;
                sum += e;
            }
#pragma unroll
            for (int o = 16; o > 0; o >>= 1)
                sum += __shfl_xor_sync(0xffffffffu, sum, o);
            const float sc = 0.03608439182435161f / sum;   // (1/sqrt(768)) / sum
#pragma unroll
            for (int j = 0; j < 7; j++) {
                const int k = lane + 32 * j;
                if (k < S_) attw[ri * ATTW + k] = acc[ri][j] * sc;
            }
        }
        __syncwarp();

        const int d0 = lane * 2;
        float o00 = 0.f, o01 = 0.f, o10 = 0.f, o11 = 0.f;
        float o20 = 0.f, o21 = 0.f, o30 = 0.f, o31 = 0.f;
#pragma unroll 4
        for (int k = 0; k < S_; k++) {
            const float2 v = *(const float2*)(Vs + k * HD_ + d0);
            const float a0 = attw[0 * ATTW + k];
            const float a1 = attw[1 * ATTW + k];
            const float a2 = attw[2 * ATTW + k];
            const float a3 = attw[3 * ATTW + k];
            o00 += a0 * v.x; o01 += a0 * v.y;
            o10 += a1 * v.x; o11 += a1 * v.y;
            o20 += a2 * v.x; o21 += a2 * v.y;
            o30 += a3 * v.x; o31 += a3 * v.y;
        }
        if (r0 + 0 < S_) *(float2*)(Og + base + (size_t)(r0 + 0) * HD_ + d0) = make_float2(tf32r(o00), tf32r(o01));
        if (r0 + 1 < S_) *(float2*)(Og + base + (size_t)(r0 + 1) * HD_ + d0) = make_float2(tf32r(o10), tf32r(o11));
        if (r0 + 2 < S_) *(float2*)(Og + base + (size_t)(r0 + 2) * HD_ + d0) = make_float2(tf32r(o20), tf32r(o21));
        if (r0 + 3 < S_) *(float2*)(Og + base + (size_t)(r0 + 3) * HD_ + d0) = make_float2(tf32r(o30), tf32r(o31));
        __syncwarp();
    }
}

// ---------------------------------------------------------------------------
extern "C" void kernel_launch(void* const* d_in, const int* in_sizes, int n_in,
                              void* d_out, int out_size)
{
    const float* x  = (const float*)d_in[0];
    const float* Wq = (const float*)d_in[1];
    const float* bq = (const float*)d_in[2];
    const float* Wk = (const float*)d_in[3];
    const float* bk = (const float*)d_in[4];
    const float* Wv = (const float*)d_in[5];
    const float* bv = (const float*)d_in[6];
    const float* Wo = (const float*)d_in[7];
    const float* bo = (const float*)d_in[8];

    float *Q, *K, *V, *Aa, *Xt, *Wqt, *Wkt, *Wvt, *Wpt;
    cudaGetSymbolAddress((void**)&Q,   g_Q);
    cudaGetSymbolAddress((void**)&K,   g_K);
    cudaGetSymbolAddress((void**)&V,   g_V);
    cudaGetSymbolAddress((void**)&Aa,  g_A);
    cudaGetSymbolAddress((void**)&Xt,  g_X);
    cudaGetSymbolAddress((void**)&Wqt, g_Wq);
    cudaGetSymbolAddress((void**)&Wkt, g_Wk);
    cudaGetSymbolAddress((void**)&Wvt, g_Wv);
    cudaGetSymbolAddress((void**)&Wpt, g_Wp);

    // 1) tf32-round x and the four weight matrices
    const int nx4 = (M_ * E_) / 4;
    const int nw4 = (E_ * E_) / 4;
    tf32_round_kernel<<<(nx4 + 255) / 256, 256>>>((const float4*)x,  (float4*)Xt,  nx4);
    tf32_round_kernel<<<(nw4 + 255) / 256, 256>>>((const float4*)Wq, (float4*)Wqt, nw4);
    tf32_round_kernel<<<(nw4 + 255) / 256, 256>>>((const float4*)Wk, (float4*)Wkt, nw4);
    tf32_round_kernel<<<(nw4 + 255) / 256, 256>>>((const float4*)Wv, (float4*)Wvt, nw4);
    tf32_round_kernel<<<(nw4 + 255) / 256, 256>>>((const float4*)Wo, (float4*)Wpt, nw4);

    cudaFuncSetAttribute(mma_nt_bias,
                         cudaFuncAttributeMaxDynamicSharedMemorySize, GEMM_SMEM_BYTES);

    // 2) fused Q/K/V projections (grid.z selects weight/bias/output)
    dim3 gqkv(E_ / 128, (M_ + 127) / 128, 3);   // (6, 99, 3)
    mma_nt_bias<<<gqkv, 256, GEMM_SMEM_BYTES>>>(Xt, Wqt, Wkt, Wvt, bq, bk, bv,
                                                Q, K, V, M_);

    // 3) attention
    const int smem_bytes = ATTN_SMEM_FLOATS * (int)sizeof(float);
    cudaFuncSetAttribute(attn_kernel,
                         cudaFuncAttributeMaxDynamicSharedMemorySize, smem_bytes);
    attn_kernel<<<B_ * H_, 512, smem_bytes>>>(Q, K, V, Aa);

    // 4) output projection
    dim3 gp(E_ / 128, (M_ + 127) / 128, 1);
    mma_nt_bias<<<gp, 256, GEMM_SMEM_BYTES>>>(Aa, Wpt, Wpt, Wpt, bo, bo, bo,
                                              (float*)d_out, (float*)d_out,
                                              (float*)d_out, M_);
}

// round 9
// speedup vs baseline: 2.5399x; 1.0357x over previous
#include <cuda_runtime.h>
#include <cstdint>

#define B_  64
#define S_  197
#define E_  768
#define H_  12
#define HD_ 64
#define M_  (B_ * S_)          // 12608

// Scratch buffers (allocation-free rule: __device__ globals)
__device__ float g_Q[B_ * S_ * E_];
__device__ float g_K[B_ * S_ * E_];
__device__ float g_V[B_ * S_ * E_];
__device__ float g_A[B_ * S_ * E_];   // attention output (tf32-rounded)
__device__ float g_X[B_ * S_ * E_];   // tf32-rounded x
__device__ float g_Wq[E_ * E_];
__device__ float g_Wk[E_ * E_];
__device__ float g_Wv[E_ * E_];
__device__ float g_Wp[E_ * E_];

// ---------------------------------------------------------------------------
// helpers
// ---------------------------------------------------------------------------
__device__ __forceinline__ float tf32r(float x) {
    uint32_t u;
    asm("cvt.rna.tf32.f32 %0, %1;" : "=r"(u) : "f"(x));
    return __uint_as_float(u);
}

__global__ void tf32_round_kernel(const float4* __restrict__ in,
                                  float4* __restrict__ out, int n4)
{
    int i = blockIdx.x * blockDim.x + threadIdx.x;
    if (i < n4) {
        float4 v = in[i];
        v.x = tf32r(v.x); v.y = tf32r(v.y); v.z = tf32r(v.z); v.w = tf32r(v.w);
        out[i] = v;
    }
}

// fused rounding of the 4 weight matrices (grid.y selects matrix)
__global__ void tf32_round4_kernel(
    const float4* __restrict__ s0, const float4* __restrict__ s1,
    const float4* __restrict__ s2, const float4* __restrict__ s3,
    float4* __restrict__ d0, float4* __restrict__ d1,
    float4* __restrict__ d2, float4* __restrict__ d3, int n4)
{
    const int z = blockIdx.y;
    const float4* in  = (z == 0) ? s0 : (z == 1) ? s1 : (z == 2) ? s2 : s3;
    float4*       out = (z == 0) ? d0 : (z == 1) ? d1 : (z == 2) ? d2 : d3;
    int i = blockIdx.x * blockDim.x + threadIdx.x;
    if (i < n4) {
        float4 v = in[i];
        v.x = tf32r(v.x); v.y = tf32r(v.y); v.z = tf32r(v.z); v.w = tf32r(v.w);
        out[i] = v;
    }
}

__device__ __forceinline__ void cpasync16(void* smem, const void* gmem) {
    uint32_t s = (uint32_t)__cvta_generic_to_shared(smem);
    asm volatile("cp.async.cg.shared.global [%0], [%1], 16;\n" :: "r"(s), "l"(gmem));
}

__device__ __forceinline__ void mma_tf32(float* c, const uint32_t* a, const uint32_t* b) {
    asm volatile(
        "mma.sync.aligned.m16n8k8.row.col.f32.tf32.tf32.f32 "
        "{%0,%1,%2,%3}, {%4,%5,%6,%7}, {%8,%9}, {%0,%1,%2,%3};\n"
        : "+f"(c[0]), "+f"(c[1]), "+f"(c[2]), "+f"(c[3])
        : "r"(a[0]), "r"(a[1]), "r"(a[2]), "r"(a[3]), "r"(b[0]), "r"(b[1]));
}

// ---------------------------------------------------------------------------
// TF32 tensor-core GEMM (NT): C[M,768] = A[M,768] @ W[768,768]^T + bias
// CTA tile 128x128, BK=32, 128 threads (4 warps, 2x2 grid, 64x64 per warp),
// double-buffered dynamic smem + cp.async, 2 CTAs/SM.
// Warp-tile choice minimizes smem-crossbar fragment traffic:
// 16KB*(2+2)=64KB/iter vs 96KB for the 4x2 8-warp layout.
// blockIdx.z selects (W, bias, C) -> fused QKV in one launch.
// ---------------------------------------------------------------------------
#define GBK 32
#define SPAD 36    // padded smem row stride (floats)
#define GEMM_SMEM_BYTES (2 * 2 * 128 * SPAD * 4)   // As+Bs, double buffered: 73728

__global__ __launch_bounds__(128, 2) void mma_nt_bias(
    const float* __restrict__ A,
    const float* __restrict__ W0, const float* __restrict__ W1,
    const float* __restrict__ W2,
    const float* __restrict__ b0, const float* __restrict__ b1,
    const float* __restrict__ b2,
    float* __restrict__ C0, float* __restrict__ C1, float* __restrict__ C2,
    int M)
{
    constexpr int K = 768, N = 768;
    extern __shared__ float smg[];
    float* As = smg;                       // [2][128][SPAD]
    float* Bs = smg + 2 * 128 * SPAD;      // [2][128][SPAD]

    const int tid = threadIdx.x;
    const int bm  = blockIdx.y, bn = blockIdx.x, z = blockIdx.z;
    const int wid = tid >> 5, lane = tid & 31;
    const int gid = lane >> 2, tig = lane & 3;
    const int r0  = (wid & 1) * 64;      // warp row offset within tile
    const int n0  = (wid >> 1) * 64;     // warp col offset within tile

    const float* Wt   = (z == 0) ? W0 : (z == 1) ? W1 : W2;
    const float* bias = (z == 0) ? b0 : (z == 1) ? b1 : b2;
    float*       C    = (z == 0) ? C0 : (z == 1) ? C1 : C2;

    float c[4][8][4] = {};   // 4 m-tiles (16 rows) x 8 n-tiles (8 cols)

    // per-thread load coords: j = tid + 128*i (i<8): row = j>>3, col4 = j&7
    int lrow[8], lc4[8];
    const float* aSrc[8];
    const float* bSrc[8];
#pragma unroll
    for (int i = 0; i < 8; i++) {
        int j = tid + 128 * i;
        lrow[i] = j >> 3;
        lc4[i]  = (j & 7) * 4;
        int ar = bm * 128 + lrow[i]; if (ar >= M) ar = M - 1;
        aSrc[i] = A  + (size_t)ar * K + lc4[i];
        bSrc[i] = Wt + (size_t)(bn * 128 + lrow[i]) * K + lc4[i];
    }

    // prefetch stage 0
#pragma unroll
    for (int i = 0; i < 8; i++) {
        cpasync16(&As[(size_t)lrow[i] * SPAD + lc4[i]], aSrc[i]);
        cpasync16(&Bs[(size_t)lrow[i] * SPAD + lc4[i]], bSrc[i]);
    }
    asm volatile("cp.async.commit_group;\n");

    int buf = 0;
    for (int it = 0; it < K / GBK; it++) {
        if (it + 1 < K / GBK) {
            const int kn = (it + 1) * GBK;
            float* An = As + (size_t)(buf ^ 1) * 128 * SPAD;
            float* Bn = Bs + (size_t)(buf ^ 1) * 128 * SPAD;
#pragma unroll
            for (int i = 0; i < 8; i++) {
                cpasync16(&An[(size_t)lrow[i] * SPAD + lc4[i]], aSrc[i] + kn);
                cpasync16(&Bn[(size_t)lrow[i] * SPAD + lc4[i]], bSrc[i] + kn);
            }
            asm volatile("cp.async.commit_group;\n");
            asm volatile("cp.async.wait_group 1;\n");
        } else {
            asm volatile("cp.async.wait_group 0;\n");
        }
        __syncthreads();

        const float* Ac = As + (size_t)buf * 128 * SPAD;
        const float* Bc = Bs + (size_t)buf * 128 * SPAD;
#pragma unroll
        for (int kk = 0; kk < 4; kk++) {
            const int kb = kk * 8;
            uint32_t a[4][4], b[8][2];
#pragma unroll
            for (int t = 0; t < 4; t++) {
                const float* p = &Ac[(size_t)(r0 + t * 16 + gid) * SPAD + kb + tig];
                a[t][0] = __float_as_uint(p[0]);
                a[t][1] = __float_as_uint(p[8 * SPAD]);
                a[t][2] = __float_as_uint(p[4]);
                a[t][3] = __float_as_uint(p[8 * SPAD + 4]);
            }
#pragma unroll
            for (int u = 0; u < 8; u++) {
                const float* p = &Bc[(size_t)(n0 + u * 8 + gid) * SPAD + kb + tig];
                b[u][0] = __float_as_uint(p[0]);
                b[u][1] = __float_as_uint(p[4]);
            }
#pragma unroll
            for (int t = 0; t < 4; t++)
#pragma unroll
                for (int u = 0; u < 8; u++)
                    mma_tf32(c[t][u], a[t], b[u]);
        }
        __syncthreads();
        buf ^= 1;
    }

    // epilogue: bias + guarded stores
#pragma unroll
    for (int t = 0; t < 4; t++) {
        const int row0 = bm * 128 + r0 + t * 16 + gid;
#pragma unroll
        for (int u = 0; u < 8; u++) {
            const int col = bn * 128 + n0 + u * 8 + 2 * tig;
            const float bx = bias[col], by = bias[col + 1];
            if (row0 < M)
                *(float2*)&C[(size_t)row0 * N + col] =
                    make_float2(c[t][u][0] + bx, c[t][u][1] + by);
            if (row0 + 8 < M)
                *(float2*)&C[(size_t)(row0 + 8) * N + col] =
                    make_float2(c[t][u][2] + bx, c[t][u][3] + by);
        }
    }
}

// ---------------------------------------------------------------------------
// Attention: one CTA per (b, h), 512 threads (16 warps x 4 query rows/sweep).
// Faithful-quirk head split (raw view, no transpose); softmax FIRST then /sqrt(E).
// Output rounded to tf32 so the proj GEMM consumes it directly.
// ---------------------------------------------------------------------------
#define KPAD 68
#define ATTW 200
#define NWARP 16
#define ATTN_SMEM_FLOATS (S_ * HD_ + S_ * KPAD + S_ * HD_ + NWARP * 4 * ATTW)

__global__ __launch_bounds__(512, 1) void attn_kernel(
    const float* __restrict__ Qg, const float* __restrict__ Kg,
    const float* __restrict__ Vg, float* __restrict__ Og)
{
    extern __shared__ float sm[];
    float* Qs = sm;
    float* Ks = Qs + S_ * HD_;
    float* Vs = Ks + S_ * KPAD;
    float* Aw = Vs + S_ * HD_;

    const int tid = threadIdx.x;
    const size_t base = (size_t)blockIdx.x * (S_ * HD_);

    const float4* Q4 = (const float4*)(Qg + base);
    const float4* K4 = (const float4*)(Kg + base);
    const float4* V4 = (const float4*)(Vg + base);
    for (int i = tid; i < S_ * (HD_ / 4); i += 512) {
        ((float4*)Qs)[i] = Q4[i];
        ((float4*)Vs)[i] = V4[i];
        const int row = i >> 4, c = i & 15;
        ((float4*)Ks)[row * (KPAD / 4) + c] = K4[i];
    }
    __syncthreads();

    const int w = tid >> 5, lane = tid & 31;
    float* attw = Aw + w * (4 * ATTW);
    const float4* Qs4 = (const float4*)Qs;
    const float4* Ks4 = (const float4*)Ks;

    int kk[7];
#pragma unroll
    for (int j = 0; j < 7; j++) {
        int k = lane + 32 * j;
        kk[j] = k < S_ ? k : (S_ - 1);
    }

    for (int base_r = 0; base_r < S_; base_r += 4 * NWARP) {
        const int r0 = base_r + w * 4;
        if (r0 >= S_) break;

        int rr[4];
#pragma unroll
        for (int ri = 0; ri < 4; ri++) {
            int r = r0 + ri;
            rr[ri] = r < S_ ? r : (S_ - 1);
        }

        float acc[4][7];
#pragma unroll
        for (int ri = 0; ri < 4; ri++)
#pragma unroll
            for (int j = 0; j < 7; j++) acc[ri][j] = 0.f;

#pragma unroll
        for (int d4 = 0; d4 < HD_ / 4; d4++) {
            const float4 q0 = Qs4[rr[0] * 16 + d4];
            const float4 q1 = Qs4[rr[1] * 16 + d4];
            const float4 q2 = Qs4[rr[2] * 16 + d4];
            const float4 q3 = Qs4[rr[3] * 16 + d4];
#pragma unroll
            for (int j = 0; j < 7; j++) {
                const float4 kv = Ks4[kk[j] * (KPAD / 4) + d4];
                acc[0][j] += q0.x * kv.x + q0.y * kv.y + q0.z * kv.z + q0.w * kv.w;
                acc[1][j] += q1.x * kv.x + q1.y * kv.y + q1.z * kv.z + q1.w * kv.w;
                acc[2][j] += q2.x * kv.x + q2.y * kv.y + q2.z * kv.z + q2.w * kv.w;
                acc[3][j] += q3.x * kv.x + q3.y * kv.y + q3.z * kv.z + q3.w * kv.w;
            }
        }

#pragma unroll
        for (int ri = 0; ri < 4; ri++) {
            if (r0 + ri >= S_) break;
            float mx = -1e30f;
#pragma unroll
            for (int j = 0; j < 7; j++)
                if (lane + 32 * j < S_) mx = fmaxf(mx, acc[ri][j]);
#pragma unroll
            for (int o = 16; o > 0; o >>= 1)
                mx = fmaxf(mx, __shfl_xor_sync(0xffffffffu, mx, o));
            float sum = 0.f;
#pragma unroll
            for (int j = 0; j < 7; j++) {
                const float e = (lane + 32 * j < S_) ? __expf(acc[ri][j] - mx) : 0.f;
                acc[ri][j] = e;
                sum += e;
            }
#pragma unroll
            for (int o = 16; o > 0; o >>= 1)
                sum += __shfl_xor_sync(0xffffffffu, sum, o);
            const float sc = 0.03608439182435161f / sum;   // (1/sqrt(768)) / sum
#pragma unroll
            for (int j = 0; j < 7; j++) {
                const int k = lane + 32 * j;
                if (k < S_) attw[ri * ATTW + k] = acc[ri][j] * sc;
            }
        }
        __syncwarp();

        const int d0 = lane * 2;
        float o00 = 0.f, o01 = 0.f, o10 = 0.f, o11 = 0.f;
        float o20 = 0.f, o21 = 0.f, o30 = 0.f, o31 = 0.f;
#pragma unroll 4
        for (int k = 0; k < S_; k++) {
            const float2 v = *(const float2*)(Vs + k * HD_ + d0);
            const float a0 = attw[0 * ATTW + k];
            const float a1 = attw[1 * ATTW + k];
            const float a2 = attw[2 * ATTW + k];
            const float a3 = attw[3 * ATTW + k];
            o00 += a0 * v.x; o01 += a0 * v.y;
            o10 += a1 * v.x; o11 += a1 * v.y;
            o20 += a2 * v.x; o21 += a2 * v.y;
            o30 += a3 * v.x; o31 += a3 * v.y;
        }
        if (r0 + 0 < S_) *(float2*)(Og + base + (size_t)(r0 + 0) * HD_ + d0) = make_float2(tf32r(o00), tf32r(o01));
        if (r0 + 1 < S_) *(float2*)(Og + base + (size_t)(r0 + 1) * HD_ + d0) = make_float2(tf32r(o10), tf32r(o11));
        if (r0 + 2 < S_) *(float2*)(Og + base + (size_t)(r0 + 2) * HD_ + d0) = make_float2(tf32r(o20), tf32r(o21));
        if (r0 + 3 < S_) *(float2*)(Og + base + (size_t)(r0 + 3) * HD_ + d0) = make_float2(tf32r(o30), tf32r(o31));
        __syncwarp();
    }
}

// ---------------------------------------------------------------------------
extern "C" void kernel_launch(void* const* d_in, const int* in_sizes, int n_in,
                              void* d_out, int out_size)
{
    const float* x  = (const float*)d_in[0];
    const float* Wq = (const float*)d_in[1];
    const float* bq = (const float*)d_in[2];
    const float* Wk = (const float*)d_in[3];
    const float* bk = (const float*)d_in[4];
    const float* Wv = (const float*)d_in[5];
    const float* bv = (const float*)d_in[6];
    const float* Wo = (const float*)d_in[7];
    const float* bo = (const float*)d_in[8];

    float *Q, *K, *V, *Aa, *Xt, *Wqt, *Wkt, *Wvt, *Wpt;
    cudaGetSymbolAddress((void**)&Q,   g_Q);
    cudaGetSymbolAddress((void**)&K,   g_K);
    cudaGetSymbolAddress((void**)&V,   g_V);
    cudaGetSymbolAddress((void**)&Aa,  g_A);
    cudaGetSymbolAddress((void**)&Xt,  g_X);
    cudaGetSymbolAddress((void**)&Wqt, g_Wq);
    cudaGetSymbolAddress((void**)&Wkt, g_Wk);
    cudaGetSymbolAddress((void**)&Wvt, g_Wv);
    cudaGetSymbolAddress((void**)&Wpt, g_Wp);

    // 1) tf32-round x and the four weight matrices (weights fused, grid.y=4)
    const int nx4 = (M_ * E_) / 4;
    const int nw4 = (E_ * E_) / 4;
    tf32_round_kernel<<<(nx4 + 255) / 256, 256>>>((const float4*)x, (float4*)Xt, nx4);
    dim3 gw((nw4 + 255) / 256, 4);
    tf32_round4_kernel<<<gw, 256>>>(
        (const float4*)Wq, (const float4*)Wk, (const float4*)Wv, (const float4*)Wo,
        (float4*)Wqt, (float4*)Wkt, (float4*)Wvt, (float4*)Wpt, nw4);

    cudaFuncSetAttribute(mma_nt_bias,
                         cudaFuncAttributeMaxDynamicSharedMemorySize, GEMM_SMEM_BYTES);

    // 2) fused Q/K/V projections (grid.z selects weight/bias/output)
    dim3 gqkv(E_ / 128, (M_ + 127) / 128, 3);   // (6, 99, 3)
    mma_nt_bias<<<gqkv, 128, GEMM_SMEM_BYTES>>>(Xt, Wqt, Wkt, Wvt, bq, bk, bv,
                                                Q, K, V, M_);

    // 3) attention
    const int smem_bytes = ATTN_SMEM_FLOATS * (int)sizeof(float);
    cudaFuncSetAttribute(attn_kernel,
                         cudaFuncAttributeMaxDynamicSharedMemorySize, smem_bytes);
    attn_kernel<<<B_ * H_, 512, smem_bytes>>>(Q, K, V, Aa);

    // 4) output projection
    dim3 gp(E_ / 128, (M_ + 127) / 128, 1);
    mma_nt_bias<<<gp, 128, GEMM_SMEM_BYTES>>>(Aa, Wpt, Wpt, Wpt, bo, bo, bo,
                                              (float*)d_out, (float*)d_out,
                                              (float*)d_out, M_);
}

// round 10
// speedup vs baseline: 3.4817x; 1.3708x over previous
#include <cuda_runtime.h>
#include <cstdint>

#define B_  64
#define S_  197
#define E_  768
#define H_  12
#define HD_ 64
#define M_  (B_ * S_)          // 12608

// Scratch buffers (allocation-free rule: __device__ globals)
__device__ float g_Q[B_ * S_ * E_];
__device__ float g_K[B_ * S_ * E_];
__device__ float g_V[B_ * S_ * E_];
__device__ float g_A[B_ * S_ * E_];   // attention output (tf32-rounded)
__device__ float g_X[B_ * S_ * E_];   // tf32-rounded x
__device__ float g_Wq[E_ * E_];
__device__ float g_Wk[E_ * E_];
__device__ float g_Wv[E_ * E_];
__device__ float g_Wp[E_ * E_];

// ---------------------------------------------------------------------------
// helpers
// ---------------------------------------------------------------------------
__device__ __forceinline__ float tf32r(float x) {
    uint32_t u;
    asm("cvt.rna.tf32.f32 %0, %1;" : "=r"(u) : "f"(x));
    return __uint_as_float(u);
}

__global__ void tf32_round_kernel(const float4* __restrict__ in,
                                  float4* __restrict__ out, int n4)
{
    int i = blockIdx.x * blockDim.x + threadIdx.x;
    if (i < n4) {
        float4 v = in[i];
        v.x = tf32r(v.x); v.y = tf32r(v.y); v.z = tf32r(v.z); v.w = tf32r(v.w);
        out[i] = v;
    }
}

// fused rounding of the 4 weight matrices (grid.y selects matrix)
__global__ void tf32_round4_kernel(
    const float4* __restrict__ s0, const float4* __restrict__ s1,
    const float4* __restrict__ s2, const float4* __restrict__ s3,
    float4* __restrict__ d0, float4* __restrict__ d1,
    float4* __restrict__ d2, float4* __restrict__ d3, int n4)
{
    const int z = blockIdx.y;
    const float4* in  = (z == 0) ? s0 : (z == 1) ? s1 : (z == 2) ? s2 : s3;
    float4*       out = (z == 0) ? d0 : (z == 1) ? d1 : (z == 2) ? d2 : d3;
    int i = blockIdx.x * blockDim.x + threadIdx.x;
    if (i < n4) {
        float4 v = in[i];
        v.x = tf32r(v.x); v.y = tf32r(v.y); v.z = tf32r(v.z); v.w = tf32r(v.w);
        out[i] = v;
    }
}

__device__ __forceinline__ void cpasync16(void* smem, const void* gmem) {
    uint32_t s = (uint32_t)__cvta_generic_to_shared(smem);
    asm volatile("cp.async.cg.shared.global [%0], [%1], 16;\n" :: "r"(s), "l"(gmem));
}

__device__ __forceinline__ void mma_tf32(float* c, const uint32_t* a, const uint32_t* b) {
    asm volatile(
        "mma.sync.aligned.m16n8k8.row.col.f32.tf32.tf32.f32 "
        "{%0,%1,%2,%3}, {%4,%5,%6,%7}, {%8,%9}, {%0,%1,%2,%3};\n"
        : "+f"(c[0]), "+f"(c[1]), "+f"(c[2]), "+f"(c[3])
        : "r"(a[0]), "r"(a[1]), "r"(a[2]), "r"(a[3]), "r"(b[0]), "r"(b[1]));
}

// ---------------------------------------------------------------------------
// TF32 tensor-core GEMM (NT): C[M,768] = A[M,768] @ W[768,768]^T + bias
// CTA tile 128x128, BK=32, 128 threads (4 warps, 2x2 grid, 64x64 per warp),
// double-buffered dynamic smem + cp.async, 2 CTAs/SM.
// rnd!=0: tf32-round outputs (QKV path, feeds tensor-core attention).
// ---------------------------------------------------------------------------
#define GBK 32
#define SPAD 36    // padded smem row stride (floats)
#define GEMM_SMEM_BYTES (2 * 2 * 128 * SPAD * 4)   // As+Bs, double buffered: 73728

__global__ __launch_bounds__(128, 2) void mma_nt_bias(
    const float* __restrict__ A,
    const float* __restrict__ W0, const float* __restrict__ W1,
    const float* __restrict__ W2,
    const float* __restrict__ b0, const float* __restrict__ b1,
    const float* __restrict__ b2,
    float* __restrict__ C0, float* __restrict__ C1, float* __restrict__ C2,
    int M, int rnd)
{
    constexpr int K = 768, N = 768;
    extern __shared__ float smg[];
    float* As = smg;                       // [2][128][SPAD]
    float* Bs = smg + 2 * 128 * SPAD;      // [2][128][SPAD]

    const int tid = threadIdx.x;
    const int bm  = blockIdx.y, bn = blockIdx.x, z = blockIdx.z;
    const int wid = tid >> 5, lane = tid & 31;
    const int gid = lane >> 2, tig = lane & 3;
    const int r0  = (wid & 1) * 64;
    const int n0  = (wid >> 1) * 64;

    const float* Wt   = (z == 0) ? W0 : (z == 1) ? W1 : W2;
    const float* bias = (z == 0) ? b0 : (z == 1) ? b1 : b2;
    float*       C    = (z == 0) ? C0 : (z == 1) ? C1 : C2;

    float c[4][8][4] = {};

    int lrow[8], lc4[8];
    const float* aSrc[8];
    const float* bSrc[8];
#pragma unroll
    for (int i = 0; i < 8; i++) {
        int j = tid + 128 * i;
        lrow[i] = j >> 3;
        lc4[i]  = (j & 7) * 4;
        int ar = bm * 128 + lrow[i]; if (ar >= M) ar = M - 1;
        aSrc[i] = A  + (size_t)ar * K + lc4[i];
        bSrc[i] = Wt + (size_t)(bn * 128 + lrow[i]) * K + lc4[i];
    }

#pragma unroll
    for (int i = 0; i < 8; i++) {
        cpasync16(&As[(size_t)lrow[i] * SPAD + lc4[i]], aSrc[i]);
        cpasync16(&Bs[(size_t)lrow[i] * SPAD + lc4[i]], bSrc[i]);
    }
    asm volatile("cp.async.commit_group;\n");

    int buf = 0;
    for (int it = 0; it < K / GBK; it++) {
        if (it + 1 < K / GBK) {
            const int kn = (it + 1) * GBK;
            float* An = As + (size_t)(buf ^ 1) * 128 * SPAD;
            float* Bn = Bs + (size_t)(buf ^ 1) * 128 * SPAD;
#pragma unroll
            for (int i = 0; i < 8; i++) {
                cpasync16(&An[(size_t)lrow[i] * SPAD + lc4[i]], aSrc[i] + kn);
                cpasync16(&Bn[(size_t)lrow[i] * SPAD + lc4[i]], bSrc[i] + kn);
            }
            asm volatile("cp.async.commit_group;\n");
            asm volatile("cp.async.wait_group 1;\n");
        } else {
            asm volatile("cp.async.wait_group 0;\n");
        }
        __syncthreads();

        const float* Ac = As + (size_t)buf * 128 * SPAD;
        const float* Bc = Bs + (size_t)buf * 128 * SPAD;
#pragma unroll
        for (int kk = 0; kk < 4; kk++) {
            const int kb = kk * 8;
            uint32_t a[4][4], b[8][2];
#pragma unroll
            for (int t = 0; t < 4; t++) {
                const float* p = &Ac[(size_t)(r0 + t * 16 + gid) * SPAD + kb + tig];
                a[t][0] = __float_as_uint(p[0]);
                a[t][1] = __float_as_uint(p[8 * SPAD]);
                a[t][2] = __float_as_uint(p[4]);
                a[t][3] = __float_as_uint(p[8 * SPAD + 4]);
            }
#pragma unroll
            for (int u = 0; u < 8; u++) {
                const float* p = &Bc[(size_t)(n0 + u * 8 + gid) * SPAD + kb + tig];
                b[u][0] = __float_as_uint(p[0]);
                b[u][1] = __float_as_uint(p[4]);
            }
#pragma unroll
            for (int t = 0; t < 4; t++)
#pragma unroll
                for (int u = 0; u < 8; u++)
                    mma_tf32(c[t][u], a[t], b[u]);
        }
        __syncthreads();
        buf ^= 1;
    }

#pragma unroll
    for (int t = 0; t < 4; t++) {
        const int row0 = bm * 128 + r0 + t * 16 + gid;
#pragma unroll
        for (int u = 0; u < 8; u++) {
            const int col = bn * 128 + n0 + u * 8 + 2 * tig;
            const float bx = bias[col], by = bias[col + 1];
            float v0 = c[t][u][0] + bx, v1 = c[t][u][1] + by;
            float v2 = c[t][u][2] + bx, v3 = c[t][u][3] + by;
            if (rnd) { v0 = tf32r(v0); v1 = tf32r(v1); v2 = tf32r(v2); v3 = tf32r(v3); }
            if (row0 < M)
                *(float2*)&C[(size_t)row0 * N + col] = make_float2(v0, v1);
            if (row0 + 8 < M)
                *(float2*)&C[(size_t)(row0 + 8) * N + col] = make_float2(v2, v3);
        }
    }
}

// ---------------------------------------------------------------------------
// Tensor-core attention: one CTA per (b, h), 256 threads (8 warps).
// Each warp owns a 16-row query tile (13 tiles). Energy and P@V via
// m16n8k8 tf32 mma. Faithful-quirk head split (raw view); softmax FIRST,
// then /sqrt(E). Q/K/V arrive tf32-rounded from the GEMM epilogue; P is
// tf32-rounded before the PV mma; outputs tf32-rounded for the proj GEMM.
// Padding 68 makes all fragment LDS conflict-free (bank = 4*gid+tig).
// ---------------------------------------------------------------------------
#define QPAD 68
#define CPAD 44
#define ATTN_SMEM_FLOATS (208 * QPAD + 200 * QPAD + 200 * QPAD + 8 * 16 * CPAD)

__global__ __launch_bounds__(256, 1) void attn_tc_kernel(
    const float* __restrict__ Qg, const float* __restrict__ Kg,
    const float* __restrict__ Vg, float* __restrict__ Og)
{
    extern __shared__ float sm[];
    float* Qs = sm;                    // 208 rows x QPAD
    float* Ks = Qs + 208 * QPAD;       // 200 rows x QPAD (rows 197-199 zero)
    float* Vs = Ks + 200 * QPAD;       // 200 rows x QPAD (rows 197-199 zero)
    float* Pb = Vs + 200 * QPAD;       // 8 warps x 16 x CPAD

    const int tid = threadIdx.x;
    const size_t base = (size_t)blockIdx.x * (S_ * HD_);

    // stage Q/K/V (row stride QPAD floats = 17 float4, 16B aligned)
    const float4* Q4 = (const float4*)(Qg + base);
    const float4* K4 = (const float4*)(Kg + base);
    const float4* V4 = (const float4*)(Vg + base);
    for (int i = tid; i < S_ * 16; i += 256) {
        const int row = i >> 4, cc = i & 15;
        ((float4*)Qs)[row * 17 + cc] = Q4[i];
        ((float4*)Ks)[row * 17 + cc] = K4[i];
        ((float4*)Vs)[row * 17 + cc] = V4[i];
    }
    // zero pad rows 197..199 of K and V
    if (tid < 102) {
        const int a = tid / 51, r = 197 + (tid % 51) / 17, cc = tid % 17;
        float* dst = (a == 0) ? Ks : Vs;
        ((float4*)dst)[r * 17 + cc] = make_float4(0.f, 0.f, 0.f, 0.f);
    }
    __syncthreads();

    const int wid = tid >> 5, lane = tid & 31;
    const int gid = lane >> 2, tig = lane & 3;
    float* Pc = Pb + wid * (16 * CPAD);

    for (int t = wid; t < 13; t += 8) {
        const int r0 = t * 16;

        // ---- Q A-fragments (held in regs for all 25 n-tiles) ----
        uint32_t qa[8][4];
#pragma unroll
        for (int ks = 0; ks < 8; ks++) {
            const float* p = &Qs[(size_t)(r0 + gid) * QPAD + 8 * ks + tig];
            qa[ks][0] = __float_as_uint(p[0]);
            qa[ks][1] = __float_as_uint(p[8 * QPAD]);
            qa[ks][2] = __float_as_uint(p[4]);
            qa[ks][3] = __float_as_uint(p[8 * QPAD + 4]);
        }

        // ---- energy: 25 n-tiles x 8 k-steps ----
        float c[25][4];
#pragma unroll
        for (int j = 0; j < 25; j++)
#pragma unroll
            for (int e = 0; e < 4; e++) c[j][e] = 0.f;

#pragma unroll
        for (int ks = 0; ks < 8; ks++) {
#pragma unroll
            for (int j = 0; j < 25; j++) {
                uint32_t b[2];
                const float* p = &Ks[(size_t)(8 * j + gid) * QPAD + 8 * ks + tig];
                b[0] = __float_as_uint(p[0]);
                b[1] = __float_as_uint(p[4]);
                mma_tf32(c[j], qa[ks], b);
            }
        }

        // ---- mask cols >= 197 (last n-tile covers 192..199) ----
        {
            const int col0 = 192 + 2 * tig;
            if (col0     >= S_) { c[24][0] = -INFINITY; c[24][2] = -INFINITY; }
            if (col0 + 1 >= S_) { c[24][1] = -INFINITY; c[24][3] = -INFINITY; }
        }

        // ---- softmax (rows rA = r0+gid via c0/c1, rB = rA+8 via c2/c3) ----
        float mxA = -INFINITY, mxB = -INFINITY;
#pragma unroll
        for (int j = 0; j < 25; j++) {
            mxA = fmaxf(mxA, fmaxf(c[j][0], c[j][1]));
            mxB = fmaxf(mxB, fmaxf(c[j][2], c[j][3]));
        }
        mxA = fmaxf(mxA, __shfl_xor_sync(0xffffffffu, mxA, 1));
        mxA = fmaxf(mxA, __shfl_xor_sync(0xffffffffu, mxA, 2));
        mxB = fmaxf(mxB, __shfl_xor_sync(0xffffffffu, mxB, 1));
        mxB = fmaxf(mxB, __shfl_xor_sync(0xffffffffu, mxB, 2));

        float sA = 0.f, sB = 0.f;
#pragma unroll
        for (int j = 0; j < 25; j++) {
            c[j][0] = __expf(c[j][0] - mxA);
            c[j][1] = __expf(c[j][1] - mxA);
            sA += c[j][0] + c[j][1];
            c[j][2] = __expf(c[j][2] - mxB);
            c[j][3] = __expf(c[j][3] - mxB);
            sB += c[j][2] + c[j][3];
        }
        sA += __shfl_xor_sync(0xffffffffu, sA, 1);
        sA += __shfl_xor_sync(0xffffffffu, sA, 2);
        sB += __shfl_xor_sync(0xffffffffu, sB, 1);
        sB += __shfl_xor_sync(0xffffffffu, sB, 2);
        const float scA = 0.03608439182435161f / sA;   // (1/sqrt(768)) / sum
        const float scB = 0.03608439182435161f / sB;

        // ---- out = P @ V : 5 chunks of 5 k-tiles through per-warp smem ----
        float o[8][4];
#pragma unroll
        for (int nj = 0; nj < 8; nj++)
#pragma unroll
            for (int e = 0; e < 4; e++) o[nj][e] = 0.f;

#pragma unroll
        for (int ch = 0; ch < 5; ch++) {
#pragma unroll
            for (int jj = 0; jj < 5; jj++) {
                const int j = ch * 5 + jj;
                *(float2*)&Pc[gid * CPAD + 8 * jj + 2 * tig] =
                    make_float2(tf32r(c[j][0] * scA), tf32r(c[j][1] * scA));
                *(float2*)&Pc[(gid + 8) * CPAD + 8 * jj + 2 * tig] =
                    make_float2(tf32r(c[j][2] * scB), tf32r(c[j][3] * scB));
            }
            __syncwarp();
#pragma unroll
            for (int jj = 0; jj < 5; jj++) {
                uint32_t pa[4];
                const float* pp = &Pc[gid * CPAD + 8 * jj + tig];
                pa[0] = __float_as_uint(pp[0]);
                pa[1] = __float_as_uint(pp[8 * CPAD]);
                pa[2] = __float_as_uint(pp[4]);
                pa[3] = __float_as_uint(pp[8 * CPAD + 4]);
                const int kb = 8 * (ch * 5 + jj);
#pragma unroll
                for (int nj = 0; nj < 8; nj++) {
                    uint32_t b[2];
                    const float* vp = &Vs[(size_t)(kb + tig) * QPAD + 8 * nj + gid];
                    b[0] = __float_as_uint(vp[0]);
                    b[1] = __float_as_uint(vp[4 * QPAD]);
                    mma_tf32(o[nj], pa, b);
                }
            }
            __syncwarp();
        }

        // ---- store (tf32-rounded for the proj GEMM) ----
        const int rA = r0 + gid, rB = rA + 8;
#pragma unroll
        for (int nj = 0; nj < 8; nj++) {
            const int col = 8 * nj + 2 * tig;
            if (rA < S_)
                *(float2*)(Og + base + (size_t)rA * HD_ + col) =
                    make_float2(tf32r(o[nj][0]), tf32r(o[nj][1]));
            if (rB < S_)
                *(float2*)(Og + base + (size_t)rB * HD_ + col) =
                    make_float2(tf32r(o[nj][2]), tf32r(o[nj][3]));
        }
    }
}

// ---------------------------------------------------------------------------
extern "C" void kernel_launch(void* const* d_in, const int* in_sizes, int n_in,
                              void* d_out, int out_size)
{
    const float* x  = (const float*)d_in[0];
    const float* Wq = (const float*)d_in[1];
    const float* bq = (const float*)d_in[2];
    const float* Wk = (const float*)d_in[3];
    const float* bk = (const float*)d_in[4];
    const float* Wv = (const float*)d_in[5];
    const float* bv = (const float*)d_in[6];
    const float* Wo = (const float*)d_in[7];
    const float* bo = (const float*)d_in[8];

    float *Q, *K, *V, *Aa, *Xt, *Wqt, *Wkt, *Wvt, *Wpt;
    cudaGetSymbolAddress((void**)&Q,   g_Q);
    cudaGetSymbolAddress((void**)&K,   g_K);
    cudaGetSymbolAddress((void**)&V,   g_V);
    cudaGetSymbolAddress((void**)&Aa,  g_A);
    cudaGetSymbolAddress((void**)&Xt,  g_X);
    cudaGetSymbolAddress((void**)&Wqt, g_Wq);
    cudaGetSymbolAddress((void**)&Wkt, g_Wk);
    cudaGetSymbolAddress((void**)&Wvt, g_Wv);
    cudaGetSymbolAddress((void**)&Wpt, g_Wp);

    // 1) tf32-round x and the four weight matrices
    const int nx4 = (M_ * E_) / 4;
    const int nw4 = (E_ * E_) / 4;
    tf32_round_kernel<<<(nx4 + 255) / 256, 256>>>((const float4*)x, (float4*)Xt, nx4);
    dim3 gw((nw4 + 255) / 256, 4);
    tf32_round4_kernel<<<gw, 256>>>(
        (const float4*)Wq, (const float4*)Wk, (const float4*)Wv, (const float4*)Wo,
        (float4*)Wqt, (float4*)Wkt, (float4*)Wvt, (float4*)Wpt, nw4);

    cudaFuncSetAttribute(mma_nt_bias,
                         cudaFuncAttributeMaxDynamicSharedMemorySize, GEMM_SMEM_BYTES);

    // 2) fused Q/K/V projections (rounded outputs feed tensor-core attention)
    dim3 gqkv(E_ / 128, (M_ + 127) / 128, 3);   // (6, 99, 3)
    mma_nt_bias<<<gqkv, 128, GEMM_SMEM_BYTES>>>(Xt, Wqt, Wkt, Wvt, bq, bk, bv,
                                                Q, K, V, M_, 1);

    // 3) tensor-core attention
    const int attn_smem = ATTN_SMEM_FLOATS * (int)sizeof(float);   // ~187.9 KB
    cudaFuncSetAttribute(attn_tc_kernel,
                         cudaFuncAttributeMaxDynamicSharedMemorySize, attn_smem);
    attn_tc_kernel<<<B_ * H_, 256, attn_smem>>>(Q, K, V, Aa);

    // 4) output projection (unrounded fp32 output)
    dim3 gp(E_ / 128, (M_ + 127) / 128, 1);
    mma_nt_bias<<<gp, 128, GEMM_SMEM_BYTES>>>(Aa, Wpt, Wpt, Wpt, bo, bo, bo,
                                              (float*)d_out, (float*)d_out,
                                              (float*)d_out, M_, 0);
}

// round 14
// speedup vs baseline: 3.5014x; 1.0057x over previous
#include <cuda_runtime.h>
#include <cstdint>

#define B_  64
#define S_  197
#define E_  768
#define H_  12
#define HD_ 64
#define M_  (B_ * S_)          // 12608

// Scratch buffers (allocation-free rule: __device__ globals)
__device__ float g_Q[B_ * S_ * E_];
__device__ float g_K[B_ * S_ * E_];
__device__ float g_V[B_ * S_ * E_];
__device__ float g_A[B_ * S_ * E_];
__device__ float g_X[B_ * S_ * E_];
__device__ float g_Wq[E_ * E_];
__device__ float g_Wk[E_ * E_];
__device__ float g_Wv[E_ * E_];
__device__ float g_Wp[E_ * E_];

// ---------------------------------------------------------------------------
// helpers
// ---------------------------------------------------------------------------
__device__ __forceinline__ float tf32r(float x) {
    uint32_t u;
    asm("cvt.rna.tf32.f32 %0, %1;" : "=r"(u) : "f"(x));
    return __uint_as_float(u);
}

__global__ void tf32_round_kernel(const float4* __restrict__ in,
                                  float4* __restrict__ out, int n4)
{
    int i = blockIdx.x * blockDim.x + threadIdx.x;
    if (i < n4) {
        float4 v = in[i];
        v.x = tf32r(v.x); v.y = tf32r(v.y); v.z = tf32r(v.z); v.w = tf32r(v.w);
        out[i] = v;
    }
}

__global__ void tf32_round4_kernel(
    const float4* __restrict__ s0, const float4* __restrict__ s1,
    const float4* __restrict__ s2, const float4* __restrict__ s3,
    float4* __restrict__ d0, float4* __restrict__ d1,
    float4* __restrict__ d2, float4* __restrict__ d3, int n4)
{
    const int z = blockIdx.y;
    const float4* in  = (z == 0) ? s0 : (z == 1) ? s1 : (z == 2) ? s2 : s3;
    float4*       out = (z == 0) ? d0 : (z == 1) ? d1 : (z == 2) ? d2 : d3;
    int i = blockIdx.x * blockDim.x + threadIdx.x;
    if (i < n4) {
        float4 v = in[i];
        v.x = tf32r(v.x); v.y = tf32r(v.y); v.z = tf32r(v.z); v.w = tf32r(v.w);
        out[i] = v;
    }
}

__device__ __forceinline__ void cpasync16(void* smem, const void* gmem) {
    uint32_t s = (uint32_t)__cvta_generic_to_shared(smem);
    asm volatile("cp.async.cg.shared.global [%0], [%1], 16;\n" :: "r"(s), "l"(gmem));
}

__device__ __forceinline__ void mma_tf32(float* c, const uint32_t* a, const uint32_t* b) {
    asm volatile(
        "mma.sync.aligned.m16n8k8.row.col.f32.tf32.tf32.f32 "
        "{%0,%1,%2,%3}, {%4,%5,%6,%7}, {%8,%9}, {%0,%1,%2,%3};\n"
        : "+f"(c[0]), "+f"(c[1]), "+f"(c[2]), "+f"(c[3])
        : "r"(a[0]), "r"(a[1]), "r"(a[2]), "r"(a[3]), "r"(b[0]), "r"(b[1]));
}

// ---------------------------------------------------------------------------
// TF32 tensor-core GEMM (NT): C[M,768] = A[M,768] @ W[768,768]^T + bias
// CTA tile 128x128, BK=32, 128 threads (4 warps, 2x2 grid, 64x64 per warp),
// 3-stage cp.async ring (2 iters of load-ahead), 2 CTAs/SM.
// rnd!=0: tf32-round outputs (QKV path, feeds tensor-core attention).
// ---------------------------------------------------------------------------
#define GBK 32
#define SPAD 36
#define NST 3
#define STG_FLOATS (2 * 128 * SPAD)                  // As+Bs per stage: 9216
#define GEMM_SMEM_BYTES (NST * STG_FLOATS * 4)       // 110592

__global__ __launch_bounds__(128, 2) void mma_nt_bias(
    const float* __restrict__ A,
    const float* __restrict__ W0, const float* __restrict__ W1,
    const float* __restrict__ W2,
    const float* __restrict__ b0, const float* __restrict__ b1,
    const float* __restrict__ b2,
    float* __restrict__ C0, float* __restrict__ C1, float* __restrict__ C2,
    int M, int rnd)
{
    constexpr int K = 768, N = 768;
    extern __shared__ float smg[];

    const int tid = threadIdx.x;
    const int bm  = blockIdx.y, bn = blockIdx.x, z = blockIdx.z;
    const int wid = tid >> 5, lane = tid & 31;
    const int gid = lane >> 2, tig = lane & 3;
    const int r0  = (wid & 1) * 64;
    const int n0  = (wid >> 1) * 64;

    const float* Wt   = (z == 0) ? W0 : (z == 1) ? W1 : W2;
    const float* bias = (z == 0) ? b0 : (z == 1) ? b1 : b2;
    float*       C    = (z == 0) ? C0 : (z == 1) ? C1 : C2;

    float c[4][8][4] = {};

    int lrow[8], lc4[8];
    const float* aSrc[8];
    const float* bSrc[8];
#pragma unroll
    for (int i = 0; i < 8; i++) {
        int j = tid + 128 * i;
        lrow[i] = j >> 3;
        lc4[i]  = (j & 7) * 4;
        int ar = bm * 128 + lrow[i]; if (ar >= M) ar = M - 1;
        aSrc[i] = A  + (size_t)ar * K + lc4[i];
        bSrc[i] = Wt + (size_t)(bn * 128 + lrow[i]) * K + lc4[i];
    }

    // prologue: stages 0 and 1 in flight
#pragma unroll
    for (int s = 0; s < 2; s++) {
        float* As = smg + s * STG_FLOATS;
        float* Bs = As + 128 * SPAD;
#pragma unroll
        for (int i = 0; i < 8; i++) {
            cpasync16(&As[(size_t)lrow[i] * SPAD + lc4[i]], aSrc[i] + s * GBK);
            cpasync16(&Bs[(size_t)lrow[i] * SPAD + lc4[i]], bSrc[i] + s * GBK);
        }
        asm volatile("cp.async.commit_group;\n");
    }

    constexpr int NIT = K / GBK;   // 24
    for (int it = 0; it < NIT; it++) {
        if (it < NIT - 1) asm volatile("cp.async.wait_group 1;\n");
        else              asm volatile("cp.async.wait_group 0;\n");
        __syncthreads();

        if (it + 2 < NIT) {
            const int s = (it + 2) % NST;
            const int kn = (it + 2) * GBK;
            float* An = smg + s * STG_FLOATS;
            float* Bn = An + 128 * SPAD;
#pragma unroll
            for (int i = 0; i < 8; i++) {
                cpasync16(&An[(size_t)lrow[i] * SPAD + lc4[i]], aSrc[i] + kn);
                cpasync16(&Bn[(size_t)lrow[i] * SPAD + lc4[i]], bSrc[i] + kn);
            }
            asm volatile("cp.async.commit_group;\n");
        }

        const float* Ac = smg + (it % NST) * STG_FLOATS;
        const float* Bc = Ac + 128 * SPAD;
#pragma unroll
        for (int kk = 0; kk < 4; kk++) {
            const int kb = kk * 8;
            uint32_t a[4][4], b[8][2];
#pragma unroll
            for (int t = 0; t < 4; t++) {
                const float* p = &Ac[(size_t)(r0 + t * 16 + gid) * SPAD + kb + tig];
                a[t][0] = __float_as_uint(p[0]);
                a[t][1] = __float_as_uint(p[8 * SPAD]);
                a[t][2] = __float_as_uint(p[4]);
                a[t][3] = __float_as_uint(p[8 * SPAD + 4]);
            }
#pragma unroll
            for (int u = 0; u < 8; u++) {
                const float* p = &Bc[(size_t)(n0 + u * 8 + gid) * SPAD + kb + tig];
                b[u][0] = __float_as_uint(p[0]);
                b[u][1] = __float_as_uint(p[4]);
            }
#pragma unroll
            for (int t = 0; t < 4; t++)
#pragma unroll
                for (int u = 0; u < 8; u++)
                    mma_tf32(c[t][u], a[t], b[u]);
        }
    }

#pragma unroll
    for (int t = 0; t < 4; t++) {
        const int row0 = bm * 128 + r0 + t * 16 + gid;
#pragma unroll
        for (int u = 0; u < 8; u++) {
            const int col = bn * 128 + n0 + u * 8 + 2 * tig;
            const float bx = bias[col], by = bias[col + 1];
            float v0 = c[t][u][0] + bx, v1 = c[t][u][1] + by;
            float v2 = c[t][u][2] + bx, v3 = c[t][u][3] + by;
            if (rnd) { v0 = tf32r(v0); v1 = tf32r(v1); v2 = tf32r(v2); v3 = tf32r(v3); }
            if (row0 < M)
                *(float2*)&C[(size_t)row0 * N + col] = make_float2(v0, v1);
            if (row0 + 8 < M)
                *(float2*)&C[(size_t)(row0 + 8) * N + col] = make_float2(v2, v3);
        }
    }
}

// ---------------------------------------------------------------------------
// Tensor-core attention: one CTA per (b, h), 416 threads = 13 warps,
// EXACTLY one 16-row query tile per warp (single sweep, no imbalance).
// Q fragments reloaded per k-step (saves ~28 regs/thread vs caching).
// Faithful-quirk head split (raw view); softmax FIRST, then /sqrt(E).
// ---------------------------------------------------------------------------
#define QPAD 68
#define CPAD 44
#define ATHR 416
#define ATTN_SMEM_FLOATS (208 * QPAD + 200 * QPAD + 200 * QPAD + 13 * 16 * CPAD)

__global__ __launch_bounds__(ATHR, 1) void attn_tc_kernel(
    const float* __restrict__ Qg, const float* __restrict__ Kg,
    const float* __restrict__ Vg, float* __restrict__ Og)
{
    extern __shared__ float sm[];
    float* Qs = sm;                    // 208 x QPAD (rows >=197 garbage, unused)
    float* Ks = Qs + 208 * QPAD;       // 200 x QPAD (rows 197-199 zeroed)
    float* Vs = Ks + 200 * QPAD;       // 200 x QPAD (rows 197-199 zeroed)
    float* Pb = Vs + 200 * QPAD;       // 13 warps x 16 x CPAD

    const int tid = threadIdx.x;
    const size_t base = (size_t)blockIdx.x * (S_ * HD_);

    const float4* Q4 = (const float4*)(Qg + base);
    const float4* K4 = (const float4*)(Kg + base);
    const float4* V4 = (const float4*)(Vg + base);
    for (int i = tid; i < S_ * 16; i += ATHR) {
        const int row = i >> 4, cc = i & 15;
        ((float4*)Qs)[row * 17 + cc] = Q4[i];
        ((float4*)Ks)[row * 17 + cc] = K4[i];
        ((float4*)Vs)[row * 17 + cc] = V4[i];
    }
    if (tid < 102) {
        const int a = tid / 51, r = 197 + (tid % 51) / 17, cc = tid % 17;
        float* dst = (a == 0) ? Ks : Vs;
        ((float4*)dst)[r * 17 + cc] = make_float4(0.f, 0.f, 0.f, 0.f);
    }
    __syncthreads();

    const int wid = tid >> 5, lane = tid & 31;
    const int gid = lane >> 2, tig = lane & 3;
    float* Pc = Pb + wid * (16 * CPAD);
    const int r0 = wid * 16;           // one tile per warp, wid in [0,13)

    // ---- energy: 25 n-tiles x 8 k-steps; Q frags reloaded per k-step ----
    float c[25][4];
#pragma unroll
    for (int j = 0; j < 25; j++)
#pragma unroll
        for (int e = 0; e < 4; e++) c[j][e] = 0.f;

#pragma unroll
    for (int ks = 0; ks < 8; ks++) {
        uint32_t qa[4];
        {
            const float* p = &Qs[(size_t)(r0 + gid) * QPAD + 8 * ks + tig];
            qa[0] = __float_as_uint(p[0]);
            qa[1] = __float_as_uint(p[8 * QPAD]);
            qa[2] = __float_as_uint(p[4]);
            qa[3] = __float_as_uint(p[8 * QPAD + 4]);
        }
#pragma unroll
        for (int j = 0; j < 25; j++) {
            uint32_t b[2];
            const float* p = &Ks[(size_t)(8 * j + gid) * QPAD + 8 * ks + tig];
            b[0] = __float_as_uint(p[0]);
            b[1] = __float_as_uint(p[4]);
            mma_tf32(c[j], qa, b);
        }
    }

    // ---- mask cols >= 197 ----
    {
        const int col0 = 192 + 2 * tig;
        if (col0     >= S_) { c[24][0] = -INFINITY; c[24][2] = -INFINITY; }
        if (col0 + 1 >= S_) { c[24][1] = -INFINITY; c[24][3] = -INFINITY; }
    }

    // ---- softmax (rows rA = r0+gid via c0/c1, rB = rA+8 via c2/c3) ----
    float mxA = -INFINITY, mxB = -INFINITY;
#pragma unroll
    for (int j = 0; j < 25; j++) {
        mxA = fmaxf(mxA, fmaxf(c[j][0], c[j][1]));
        mxB = fmaxf(mxB, fmaxf(c[j][2], c[j][3]));
    }
    mxA = fmaxf(mxA, __shfl_xor_sync(0xffffffffu, mxA, 1));
    mxA = fmaxf(mxA, __shfl_xor_sync(0xffffffffu, mxA, 2));
    mxB = fmaxf(mxB, __shfl_xor_sync(0xffffffffu, mxB, 1));
    mxB = fmaxf(mxB, __shfl_xor_sync(0xffffffffu, mxB, 2));

    float sA = 0.f, sB = 0.f;
#pragma unroll
    for (int j = 0; j < 25; j++) {
        c[j][0] = __expf(c[j][0] - mxA);
        c[j][1] = __expf(c[j][1] - mxA);
        sA += c[j][0] + c[j][1];
        c[j][2] = __expf(c[j][2] - mxB);
        c[j][3] = __expf(c[j][3] - mxB);
        sB += c[j][2] + c[j][3];
    }
    sA += __shfl_xor_sync(0xffffffffu, sA, 1);
    sA += __shfl_xor_sync(0xffffffffu, sA, 2);
    sB += __shfl_xor_sync(0xffffffffu, sB, 1);
    sB += __shfl_xor_sync(0xffffffffu, sB, 2);
    const float scA = 0.03608439182435161f / sA;   // (1/sqrt(768)) / sum
    const float scB = 0.03608439182435161f / sB;

    // ---- out = P @ V : 5 chunks of 5 k-tiles through per-warp smem ----
    float o[8][4];
#pragma unroll
    for (int nj = 0; nj < 8; nj++)
#pragma unroll
        for (int e = 0; e < 4; e++) o[nj][e] = 0.f;

#pragma unroll
    for (int ch = 0; ch < 5; ch++) {
#pragma unroll
        for (int jj = 0; jj < 5; jj++) {
            const int j = ch * 5 + jj;
            *(float2*)&Pc[gid * CPAD + 8 * jj + 2 * tig] =
                make_float2(tf32r(c[j][0] * scA), tf32r(c[j][1] * scA));
            *(float2*)&Pc[(gid + 8) * CPAD + 8 * jj + 2 * tig] =
                make_float2(tf32r(c[j][2] * scB), tf32r(c[j][3] * scB));
        }
        __syncwarp();
#pragma unroll
        for (int jj = 0; jj < 5; jj++) {
            uint32_t pa[4];
            const float* pp = &Pc[gid * CPAD + 8 * jj + tig];
            pa[0] = __float_as_uint(pp[0]);
            pa[1] = __float_as_uint(pp[8 * CPAD]);
            pa[2] = __float_as_uint(pp[4]);
            pa[3] = __float_as_uint(pp[8 * CPAD + 4]);
            const int kb = 8 * (ch * 5 + jj);
#pragma unroll
            for (int nj = 0; nj < 8; nj++) {
                uint32_t b[2];
                const float* vp = &Vs[(size_t)(kb + tig) * QPAD + 8 * nj + gid];
                b[0] = __float_as_uint(vp[0]);
                b[1] = __float_as_uint(vp[4 * QPAD]);
                mma_tf32(o[nj], pa, b);
            }
        }
        __syncwarp();
    }

    // ---- store (tf32-rounded for the proj GEMM) ----
    const int rA = r0 + gid, rB = rA + 8;
#pragma unroll
    for (int nj = 0; nj < 8; nj++) {
        const int col = 8 * nj + 2 * tig;
        if (rA < S_)
            *(float2*)(Og + base + (size_t)rA * HD_ + col) =
                make_float2(tf32r(o[nj][0]), tf32r(o[nj][1]));
        if (rB < S_)
            *(float2*)(Og + base + (size_t)rB * HD_ + col) =
                make_float2(tf32r(o[nj][2]), tf32r(o[nj][3]));
    }
}

// ---------------------------------------------------------------------------
extern "C" void kernel_launch(void* const* d_in, const int* in_sizes, int n_in,
                              void* d_out, int out_size)
{
    const float* x  = (const float*)d_in[0];
    const float* Wq = (const float*)d_in[1];
    const float* bq = (const float*)d_in[2];
    const float* Wk = (const float*)d_in[3];
    const float* bk = (const float*)d_in[4];
    const float* Wv = (const float*)d_in[5];
    const float* bv = (const float*)d_in[6];
    const float* Wo = (const float*)d_in[7];
    const float* bo = (const float*)d_in[8];

    float *Q, *K, *V, *Aa, *Xt, *Wqt, *Wkt, *Wvt, *Wpt;
    cudaGetSymbolAddress((void**)&Q,   g_Q);
    cudaGetSymbolAddress((void**)&K,   g_K);
    cudaGetSymbolAddress((void**)&V,   g_V);
    cudaGetSymbolAddress((void**)&Aa,  g_A);
    cudaGetSymbolAddress((void**)&Xt,  g_X);
    cudaGetSymbolAddress((void**)&Wqt, g_Wq);
    cudaGetSymbolAddress((void**)&Wkt, g_Wk);
    cudaGetSymbolAddress((void**)&Wvt, g_Wv);
    cudaGetSymbolAddress((void**)&Wpt, g_Wp);

    // 1) tf32-round x and the four weight matrices
    const int nx4 = (M_ * E_) / 4;
    const int nw4 = (E_ * E_) / 4;
    tf32_round_kernel<<<(nx4 + 255) / 256, 256>>>((const float4*)x, (float4*)Xt, nx4);
    dim3 gw((nw4 + 255) / 256, 4);
    tf32_round4_kernel<<<gw, 256>>>(
        (const float4*)Wq, (const float4*)Wk, (const float4*)Wv, (const float4*)Wo,
        (float4*)Wqt, (float4*)Wkt, (float4*)Wvt, (float4*)Wpt, nw4);

    cudaFuncSetAttribute(mma_nt_bias,
                         cudaFuncAttributeMaxDynamicSharedMemorySize, GEMM_SMEM_BYTES);

    // 2) fused Q/K/V projections (rounded outputs feed tensor-core attention)
    dim3 gqkv(E_ / 128, (M_ + 127) / 128, 3);   // (6, 99, 3)
    mma_nt_bias<<<gqkv, 128, GEMM_SMEM_BYTES>>>(Xt, Wqt, Wkt, Wvt, bq, bk, bv,
                                                Q, K, V, M_, 1);

    // 3) tensor-core attention (13 warps, one tile each)
    const int attn_smem = ATTN_SMEM_FLOATS * (int)sizeof(float);   // ~202 KB
    cudaFuncSetAttribute(attn_tc_kernel,
                         cudaFuncAttributeMaxDynamicSharedMemorySize, attn_smem);
    attn_tc_kernel<<<B_ * H_, ATHR, attn_smem>>>(Q, K, V, Aa);

    // 4) output projection (unrounded fp32 output)
    dim3 gp(E_ / 128, (M_ + 127) / 128, 1);
    mma_nt_bias<<<gp, 128, GEMM_SMEM_BYTES>>>(Aa, Wpt, Wpt, Wpt, bo, bo, bo,
                                              (float*)d_out, (float*)d_out,
                                              (float*)d_out, M_, 0);
}

// round 15
// speedup vs baseline: 5.9934x; 1.7117x over previous
#include <cuda_runtime.h>
#include <cuda_fp16.h>
#include <cstdint>

#define B_  64
#define S_  197
#define E_  768
#define H_  12
#define HD_ 64
#define M_  (B_ * S_)          // 12608

// Scratch buffers (allocation-free rule: __device__ globals)
__device__ __half g_Q[B_ * S_ * E_];
__device__ __half g_K[B_ * S_ * E_];
__device__ __half g_V[B_ * S_ * E_];
__device__ __half g_A[B_ * S_ * E_];   // attention output (fp16)
__device__ __half g_X[B_ * S_ * E_];   // fp16 x
__device__ __half g_Wq[E_ * E_];
__device__ __half g_Wk[E_ * E_];
__device__ __half g_Wv[E_ * E_];
__device__ __half g_Wp[E_ * E_];

// ---------------------------------------------------------------------------
// helpers
// ---------------------------------------------------------------------------
__device__ __forceinline__ uint32_t pack_h2(float x, float y) {
    __half2 h = __floats2half2_rn(x, y);
    return *(uint32_t*)&h;
}

__global__ void f2h_kernel(const float4* __restrict__ in,
                           uint2* __restrict__ out, int n4)
{
    int i = blockIdx.x * blockDim.x + threadIdx.x;
    if (i < n4) {
        float4 v = in[i];
        out[i] = make_uint2(pack_h2(v.x, v.y), pack_h2(v.z, v.w));
    }
}

__global__ void f2h4_kernel(
    const float4* __restrict__ s0, const float4* __restrict__ s1,
    const float4* __restrict__ s2, const float4* __restrict__ s3,
    uint2* __restrict__ d0, uint2* __restrict__ d1,
    uint2* __restrict__ d2, uint2* __restrict__ d3, int n4)
{
    const int z = blockIdx.y;
    const float4* in = (z == 0) ? s0 : (z == 1) ? s1 : (z == 2) ? s2 : s3;
    uint2*      out = (z == 0) ? d0 : (z == 1) ? d1 : (z == 2) ? d2 : d3;
    int i = blockIdx.x * blockDim.x + threadIdx.x;
    if (i < n4) {
        float4 v = in[i];
        out[i] = make_uint2(pack_h2(v.x, v.y), pack_h2(v.z, v.w));
    }
}

__device__ __forceinline__ void cpasync16(void* smem, const void* gmem) {
    uint32_t s = (uint32_t)__cvta_generic_to_shared(smem);
    asm volatile("cp.async.cg.shared.global [%0], [%1], 16;\n" :: "r"(s), "l"(gmem));
}

// m16n8k16 fp16 mma, fp32 accumulate
__device__ __forceinline__ void mma_f16(float* c, const uint32_t* a, const uint32_t* b) {
    asm volatile(
        "mma.sync.aligned.m16n8k16.row.col.f32.f16.f16.f32 "
        "{%0,%1,%2,%3}, {%4,%5,%6,%7}, {%8,%9}, {%0,%1,%2,%3};\n"
        : "+f"(c[0]), "+f"(c[1]), "+f"(c[2]), "+f"(c[3])
        : "r"(a[0]), "r"(a[1]), "r"(a[2]), "r"(a[3]), "r"(b[0]), "r"(b[1]));
}

// ---------------------------------------------------------------------------
// FP16 tensor-core GEMM (NT): C[M,768] = A[M,768] @ W[768,768]^T + bias
// CTA tile 128x128, K chunk 64 halves/stage, 128 threads (4 warps, 2x2 of
// 64x64), 3-stage cp.async ring, 2 CTAs/SM. half_out: fp16 vs fp32 C.
// Smem rows padded to 72 halves (36 words) -> conflict-free (4*gid+tig).
// ---------------------------------------------------------------------------
#define GBK 64                                      // k-halves per stage
#define HPAD 72                                     // halves per smem row
#define NST 3
#define STG_HALVES (2 * 128 * HPAD)                 // A+B per stage: 18432
#define GEMM_SMEM_BYTES (NST * STG_HALVES * 2)      // 110592

__global__ __launch_bounds__(128, 2) void hgemm_nt(
    const __half* __restrict__ A,
    const __half* __restrict__ W0, const __half* __restrict__ W1,
    const __half* __restrict__ W2,
    const float* __restrict__ b0, const float* __restrict__ b1,
    const float* __restrict__ b2,
    void* __restrict__ C0, void* __restrict__ C1, void* __restrict__ C2,
    int M, int half_out)
{
    constexpr int K = 768, N = 768;
    extern __shared__ __half smh[];

    const int tid = threadIdx.x;
    const int bm  = blockIdx.y, bn = blockIdx.x, z = blockIdx.z;
    const int wid = tid >> 5, lane = tid & 31;
    const int gid = lane >> 2, tig = lane & 3;
    const int r0  = (wid & 1) * 64;
    const int n0  = (wid >> 1) * 64;

    const __half* Wt  = (z == 0) ? W0 : (z == 1) ? W1 : W2;
    const float* bias = (z == 0) ? b0 : (z == 1) ? b1 : b2;
    void*        C    = (z == 0) ? C0 : (z == 1) ? C1 : C2;

    float c[4][8][4] = {};

    // loads: j = tid + 128*i (i<8): row = j>>3, seg = j&7 (16B = 8 halves)
    int lrow[8], lsg[8];
    const __half* aSrc[8];
    const __half* bSrc[8];
#pragma unroll
    for (int i = 0; i < 8; i++) {
        int j = tid + 128 * i;
        lrow[i] = j >> 3;
        lsg[i]  = (j & 7) * 8;
        int ar = bm * 128 + lrow[i]; if (ar >= M) ar = M - 1;
        aSrc[i] = A  + (size_t)ar * K + lsg[i];
        bSrc[i] = Wt + (size_t)(bn * 128 + lrow[i]) * K + lsg[i];
    }

    // prologue: stages 0,1
#pragma unroll
    for (int s = 0; s < 2; s++) {
        __half* As = smh + s * STG_HALVES;
        __half* Bs = As + 128 * HPAD;
#pragma unroll
        for (int i = 0; i < 8; i++) {
            cpasync16(&As[lrow[i] * HPAD + lsg[i]], aSrc[i] + s * GBK);
            cpasync16(&Bs[lrow[i] * HPAD + lsg[i]], bSrc[i] + s * GBK);
        }
        asm volatile("cp.async.commit_group;\n");
    }

    constexpr int NIT = K / GBK;   // 12
    for (int it = 0; it < NIT; it++) {
        if (it < NIT - 1) asm volatile("cp.async.wait_group 1;\n");
        else              asm volatile("cp.async.wait_group 0;\n");
        __syncthreads();

        if (it + 2 < NIT) {
            const int s = (it + 2) % NST;
            const int kn = (it + 2) * GBK;
            __half* An = smh + s * STG_HALVES;
            __half* Bn = An + 128 * HPAD;
#pragma unroll
            for (int i = 0; i < 8; i++) {
                cpasync16(&An[lrow[i] * HPAD + lsg[i]], aSrc[i] + kn);
                cpasync16(&Bn[lrow[i] * HPAD + lsg[i]], bSrc[i] + kn);
            }
            asm volatile("cp.async.commit_group;\n");
        }

        const __half* Ac = smh + (it % NST) * STG_HALVES;
        const __half* Bc = Ac + 128 * HPAD;
#pragma unroll
        for (int kk = 0; kk < 4; kk++) {
            const int kb = kk * 16;
            uint32_t a[4][4], b[8][2];
#pragma unroll
            for (int t = 0; t < 4; t++) {
                const __half* p = &Ac[(r0 + t * 16 + gid) * HPAD + kb + 2 * tig];
                a[t][0] = *(const uint32_t*)(p);
                a[t][1] = *(const uint32_t*)(p + 8 * HPAD);
                a[t][2] = *(const uint32_t*)(p + 8);
                a[t][3] = *(const uint32_t*)(p + 8 * HPAD + 8);
            }
#pragma unroll
            for (int u = 0; u < 8; u++) {
                const __half* p = &Bc[(n0 + u * 8 + gid) * HPAD + kb + 2 * tig];
                b[u][0] = *(const uint32_t*)(p);
                b[u][1] = *(const uint32_t*)(p + 8);
            }
#pragma unroll
            for (int t = 0; t < 4; t++)
#pragma unroll
                for (int u = 0; u < 8; u++)
                    mma_f16(c[t][u], a[t], b[u]);
        }
    }

    // epilogue: bias + guarded stores (fp16 or fp32 per half_out)
#pragma unroll
    for (int t = 0; t < 4; t++) {
        const int row0 = bm * 128 + r0 + t * 16 + gid;
#pragma unroll
        for (int u = 0; u < 8; u++) {
            const int col = bn * 128 + n0 + u * 8 + 2 * tig;
            const float bx = bias[col], by = bias[col + 1];
            const float v0 = c[t][u][0] + bx, v1 = c[t][u][1] + by;
            const float v2 = c[t][u][2] + bx, v3 = c[t][u][3] + by;
            if (half_out) {
                __half* Ch = (__half*)C;
                if (row0 < M)
                    *(uint32_t*)&Ch[(size_t)row0 * N + col] = pack_h2(v0, v1);
                if (row0 + 8 < M)
                    *(uint32_t*)&Ch[(size_t)(row0 + 8) * N + col] = pack_h2(v2, v3);
            } else {
                float* Cf = (float*)C;
                if (row0 < M)
                    *(float2*)&Cf[(size_t)row0 * N + col] = make_float2(v0, v1);
                if (row0 + 8 < M)
                    *(float2*)&Cf[(size_t)(row0 + 8) * N + col] = make_float2(v2, v3);
            }
        }
    }
}

// ---------------------------------------------------------------------------
// FP16 tensor-core attention: one CTA per (b, h), 416 threads = 13 warps,
// one 16-row query tile per warp. Energy AND P@V via m16n8k16; the QK^T
// C-fragment IS the P@V A-fragment (k16 A-frag = two adjacent k8 C-frags),
// so P never touches smem. V stored transposed (Vt[d][s]) so PV B-frags are
// contiguous half2. Faithful-quirk head split; softmax FIRST then /sqrt(E).
// ---------------------------------------------------------------------------
#define ATHR 416
#define KROW 72                    // Ks row stride (halves): (36w*gid+tig) cf-free
#define VROW 216                   // Vt row stride (halves): (108w*gid+tig) cf-free
#define ATTN_SMEM_HALVES (200 * KROW + 64 * VROW)   // 14400 + 13824

__global__ __launch_bounds__(ATHR, 1) void attn_f16_kernel(
    const __half* __restrict__ Qg, const __half* __restrict__ Kg,
    const __half* __restrict__ Vg, __half* __restrict__ Og)
{
    extern __shared__ __half smA[];
    __half* Ks = smA;              // 200 x KROW
    __half* Vt = smA + 200 * KROW; // 64 x VROW  (cols 197..215 zero)

    const int tid = threadIdx.x;
    const size_t base = (size_t)blockIdx.x * (S_ * HD_);

    // phase A: zero all smem (covers K pad rows + Vt pad cols)
    for (int i = tid; i < ATTN_SMEM_HALVES / 8; i += ATHR)
        ((uint4*)smA)[i] = make_uint4(0, 0, 0, 0);
    __syncthreads();

    // phase B: stage K rows 0..196, V transposed
    const uint4* K16 = (const uint4*)(Kg + base);
    for (int i = tid; i < 197 * 8; i += ATHR) {
        const int row = i >> 3, seg = i & 7;
        *(uint4*)&Ks[row * KROW + seg * 8] = K16[i];
    }
    const __half2* V2 = (const __half2*)(Vg + base);
    for (int i = tid; i < 197 * 32; i += ATHR) {
        const int s = i >> 5, d2 = i & 31;
        const __half2 v = V2[i];
        Vt[(2 * d2)     * VROW + s] = __low2half(v);
        Vt[(2 * d2 + 1) * VROW + s] = __high2half(v);
    }
    __syncthreads();

    const int wid = tid >> 5, lane = tid & 31;
    const int gid = lane >> 2, tig = lane & 3;
    const int r0 = wid * 16;                 // wid in [0,13)
    const int rA = r0 + gid, rB = rA + 8;
    const int qrA = (rA < S_) ? rA : (S_ - 1);
    const int qrB = (rB < S_) ? rB : (S_ - 1);

    // ---- energy: 25 n-tiles x 4 k16-steps; Q frags direct from gmem ----
    float c[25][4];
#pragma unroll
    for (int j = 0; j < 25; j++)
#pragma unroll
        for (int e = 0; e < 4; e++) c[j][e] = 0.f;

#pragma unroll
    for (int ks = 0; ks < 4; ks++) {
        const int k0 = 16 * ks + 2 * tig;
        uint32_t qa[4];
        qa[0] = *(const uint32_t*)(Qg + base + (size_t)qrA * HD_ + k0);
        qa[1] = *(const uint32_t*)(Qg + base + (size_t)qrB * HD_ + k0);
        qa[2] = *(const uint32_t*)(Qg + base + (size_t)qrA * HD_ + k0 + 8);
        qa[3] = *(const uint32_t*)(Qg + base + (size_t)qrB * HD_ + k0 + 8);
#pragma unroll
        for (int j = 0; j < 25; j++) {
            uint32_t b[2];
            const __half* p = &Ks[(8 * j + gid) * KROW + 16 * ks + 2 * tig];
            b[0] = *(const uint32_t*)(p);
            b[1] = *(const uint32_t*)(p + 8);
            mma_f16(c[j], qa, b);
        }
    }

    // ---- mask cols >= 197 (n-tile 24 covers 192..199) ----
    {
        const int col0 = 192 + 2 * tig;
        if (col0     >= S_) { c[24][0] = -INFINITY; c[24][2] = -INFINITY; }
        if (col0 + 1 >= S_) { c[24][1] = -INFINITY; c[24][3] = -INFINITY; }
    }

    // ---- softmax (row rA via c0/c1, row rB via c2/c3; quad reduce) ----
    float mxA = -INFINITY, mxB = -INFINITY;
#pragma unroll
    for (int j = 0; j < 25; j++) {
        mxA = fmaxf(mxA, fmaxf(c[j][0], c[j][1]));
        mxB = fmaxf(mxB, fmaxf(c[j][2], c[j][3]));
    }
    mxA = fmaxf(mxA, __shfl_xor_sync(0xffffffffu, mxA, 1));
    mxA = fmaxf(mxA, __shfl_xor_sync(0xffffffffu, mxA, 2));
    mxB = fmaxf(mxB, __shfl_xor_sync(0xffffffffu, mxB, 1));
    mxB = fmaxf(mxB, __shfl_xor_sync(0xffffffffu, mxB, 2));

    float sA = 0.f, sB = 0.f;
#pragma unroll
    for (int j = 0; j < 25; j++) {
        c[j][0] = __expf(c[j][0] - mxA);
        c[j][1] = __expf(c[j][1] - mxA);
        sA += c[j][0] + c[j][1];
        c[j][2] = __expf(c[j][2] - mxB);
        c[j][3] = __expf(c[j][3] - mxB);
        sB += c[j][2] + c[j][3];
    }
    sA += __shfl_xor_sync(0xffffffffu, sA, 1);
    sA += __shfl_xor_sync(0xffffffffu, sA, 2);
    sB += __shfl_xor_sync(0xffffffffu, sB, 1);
    sB += __shfl_xor_sync(0xffffffffu, sB, 2);
    const float scA = 0.03608439182435161f / sA;   // (1/sqrt(768)) / sum
    const float scB = 0.03608439182435161f / sB;

    // ---- out = P @ V : 13 k16-steps; P A-frags built in registers ----
    float o[8][4];
#pragma unroll
    for (int nj = 0; nj < 8; nj++)
#pragma unroll
        for (int e = 0; e < 4; e++) o[nj][e] = 0.f;

#pragma unroll
    for (int m = 0; m < 13; m++) {
        uint32_t pa[4];
        const int j0 = 2 * m;
        pa[0] = pack_h2(c[j0][0] * scA, c[j0][1] * scA);
        pa[1] = pack_h2(c[j0][2] * scB, c[j0][3] * scB);
        if (m < 12) {
            pa[2] = pack_h2(c[j0 + 1][0] * scA, c[j0 + 1][1] * scA);
            pa[3] = pack_h2(c[j0 + 1][2] * scB, c[j0 + 1][3] * scB);
        } else {
            pa[2] = 0u; pa[3] = 0u;   // P cols 200..207 = 0
        }
        const int kb = 16 * m + 2 * tig;
#pragma unroll
        for (int nj = 0; nj < 8; nj++) {
            uint32_t b[2];
            const __half* p = &Vt[(8 * nj + gid) * VROW + kb];
            b[0] = *(const uint32_t*)(p);
            b[1] = *(const uint32_t*)(p + 8);
            mma_f16(o[nj], pa, b);
        }
    }

    // ---- store fp16 (feeds the fp16 proj GEMM) ----
#pragma unroll
    for (int nj = 0; nj < 8; nj++) {
        const int col = 8 * nj + 2 * tig;
        if (rA < S_)
            *(uint32_t*)(Og + base + (size_t)rA * HD_ + col) =
                pack_h2(o[nj][0], o[nj][1]);
        if (rB < S_)
            *(uint32_t*)(Og + base + (size_t)rB * HD_ + col) =
                pack_h2(o[nj][2], o[nj][3]);
    }
}

// ---------------------------------------------------------------------------
extern "C" void kernel_launch(void* const* d_in, const int* in_sizes, int n_in,
                              void* d_out, int out_size)
{
    const float* x  = (const float*)d_in[0];
    const float* Wq = (const float*)d_in[1];
    const float* bq = (const float*)d_in[2];
    const float* Wk = (const float*)d_in[3];
    const float* bk = (const float*)d_in[4];
    const float* Wv = (const float*)d_in[5];
    const float* bv = (const float*)d_in[6];
    const float* Wo = (const float*)d_in[7];
    const float* bo = (const float*)d_in[8];

    __half *Q, *K, *V, *Aa, *Xt, *Wqt, *Wkt, *Wvt, *Wpt;
    cudaGetSymbolAddress((void**)&Q,   g_Q);
    cudaGetSymbolAddress((void**)&K,   g_K);
    cudaGetSymbolAddress((void**)&V,   g_V);
    cudaGetSymbolAddress((void**)&Aa,  g_A);
    cudaGetSymbolAddress((void**)&Xt,  g_X);
    cudaGetSymbolAddress((void**)&Wqt, g_Wq);
    cudaGetSymbolAddress((void**)&Wkt, g_Wk);
    cudaGetSymbolAddress((void**)&Wvt, g_Wv);
    cudaGetSymbolAddress((void**)&Wpt, g_Wp);

    // 1) fp16-convert x and the four weight matrices
    const int nx4 = (M_ * E_) / 4;
    const int nw4 = (E_ * E_) / 4;
    f2h_kernel<<<(nx4 + 255) / 256, 256>>>((const float4*)x, (uint2*)Xt, nx4);
    dim3 gw((nw4 + 255) / 256, 4);
    f2h4_kernel<<<gw, 256>>>(
        (const float4*)Wq, (const float4*)Wk, (const float4*)Wv, (const float4*)Wo,
        (uint2*)Wqt, (uint2*)Wkt, (uint2*)Wvt, (uint2*)Wpt, nw4);

    cudaFuncSetAttribute(hgemm_nt,
                         cudaFuncAttributeMaxDynamicSharedMemorySize, GEMM_SMEM_BYTES);

    // 2) fused Q/K/V projections (fp16 out -> fp16 attention)
    dim3 gqkv(E_ / 128, (M_ + 127) / 128, 3);   // (6, 99, 3)
    hgemm_nt<<<gqkv, 128, GEMM_SMEM_BYTES>>>(Xt, Wqt, Wkt, Wvt, bq, bk, bv,
                                             Q, K, V, M_, 1);

    // 3) fp16 tensor-core attention
    const int attn_smem = ATTN_SMEM_HALVES * 2;   // 56448 B
    cudaFuncSetAttribute(attn_f16_kernel,
                         cudaFuncAttributeMaxDynamicSharedMemorySize, attn_smem);
    attn_f16_kernel<<<B_ * H_, ATHR, attn_smem>>>(Q, K, V, Aa);

    // 4) output projection (fp32 out)
    dim3 gp(E_ / 128, (M_ + 127) / 128, 1);
    hgemm_nt<<<gp, 128, GEMM_SMEM_BYTES>>>(Aa, Wpt, Wpt, Wpt, bo, bo, bo,
                                           (float*)d_out, (float*)d_out,
                                           (float*)d_out, M_, 0);
}